// round 1
// baseline (speedup 1.0000x reference)
#include <cuda_runtime.h>
#include <cstdint>

#define Bq 4
#define Nq 8192
#define DIMq 1024
#define Hq 16
#define DHq 64
#define GSPLIT 16

// Scratch (device globals — no allocation allowed)
__device__ float g_Gpart[GSPLIT][Bq * Hq * DHq * DHq];  // 16 MB
__device__ float g_G[Bq * Hq * DHq * DHq];              // 1 MB
__device__ float g_P[Bq * DIMq * DIMq];                 // 16 MB

// ---- packed f32x2 helpers (Blackwell FFMA2 path, PTX-only) ----
__device__ __forceinline__ unsigned long long pack2(float x) {
    unsigned long long v;
    unsigned u = __float_as_uint(x);
    asm("mov.b64 %0, {%1, %2};" : "=l"(v) : "r"(u), "r"(u));
    return v;
}
__device__ __forceinline__ unsigned long long ffma2(unsigned long long a,
                                                    unsigned long long b,
                                                    unsigned long long c) {
    unsigned long long d;
    asm("fma.rn.f32x2 %0, %1, %2, %3;" : "=l"(d) : "l"(a), "l"(b), "l"(c));
    return d;
}
__device__ __forceinline__ float2 unpack2(unsigned long long v) {
    unsigned lo, hi;
    asm("mov.b64 {%0, %1}, %2;" : "=r"(lo), "=r"(hi) : "l"(v));
    return make_float2(__uint_as_float(lo), __uint_as_float(hi));
}

// ============================================================
// Kernel 1: per-(b,h) Gram matrices G = x_h^T x_h, split over N
// grid (64 bh, GSPLIT), 256 threads; deterministic partials.
// ============================================================
__global__ __launch_bounds__(256) void gram_kernel(const float* __restrict__ x) {
    int bh = blockIdx.x;
    int sp = blockIdx.y;
    int b = bh >> 4, h = bh & 15;
    __shared__ float sx[8][64];
    int tid = threadIdx.x;
    int ty = tid >> 4, tx = tid & 15;
    int lr = tid >> 5, lc = (tid & 31) * 2;

    unsigned long long acc[4][2];
#pragma unroll
    for (int i = 0; i < 4; i++) { acc[i][0] = 0ull; acc[i][1] = 0ull; }

    const float* xb = x + ((size_t)b * Nq + (size_t)sp * (Nq / GSPLIT)) * DIMq + h * DHq;
    const int ITERS = (Nq / GSPLIT) / 8;  // 64

    for (int it = 0; it < ITERS; ++it) {
        *(float2*)&sx[lr][lc] = *(const float2*)(xb + (size_t)(it * 8 + lr) * DIMq + lc);
        __syncthreads();
#pragma unroll
        for (int r = 0; r < 8; r++) {
            float4 a4 = *(const float4*)&sx[r][ty * 4];
            ulonglong2 b2 = *(const ulonglong2*)&sx[r][tx * 4];
            unsigned long long ap;
            ap = pack2(a4.x); acc[0][0] = ffma2(ap, b2.x, acc[0][0]); acc[0][1] = ffma2(ap, b2.y, acc[0][1]);
            ap = pack2(a4.y); acc[1][0] = ffma2(ap, b2.x, acc[1][0]); acc[1][1] = ffma2(ap, b2.y, acc[1][1]);
            ap = pack2(a4.z); acc[2][0] = ffma2(ap, b2.x, acc[2][0]); acc[2][1] = ffma2(ap, b2.y, acc[2][1]);
            ap = pack2(a4.w); acc[3][0] = ffma2(ap, b2.x, acc[3][0]); acc[3][1] = ffma2(ap, b2.y, acc[3][1]);
        }
        __syncthreads();
    }

    float* dst = g_Gpart[sp] + (size_t)bh * 4096;
#pragma unroll
    for (int i = 0; i < 4; i++) {
        int row = ty * 4 + i;
        float2 v0 = unpack2(acc[i][0]);
        float2 v1 = unpack2(acc[i][1]);
        dst[row * 64 + tx * 4 + 0] = v0.x;
        dst[row * 64 + tx * 4 + 1] = v0.y;
        dst[row * 64 + tx * 4 + 2] = v1.x;
        dst[row * 64 + tx * 4 + 3] = v1.y;
    }
}

// ============================================================
// Kernel 2: deterministic reduction of Gram partials
// ============================================================
__global__ void reduceG_kernel() {
    int idx = blockIdx.x * 256 + threadIdx.x;  // 262144 total
    float s = 0.f;
#pragma unroll
    for (int p = 0; p < GSPLIT; p++) s += g_Gpart[p][idx];
    g_G[idx] = s;
}

// ============================================================
// Kernel 3: P_bh = Wq^T Wk G Wv^T Wo_h^T / N  (64x1024 per bh)
// grid (64 bh, 8 col-chunks of 128), 256 threads, dyn smem 49920B
// ============================================================
__global__ __launch_bounds__(256) void computeP_kernel(const float* __restrict__ Wq,
                                                       const float* __restrict__ Wk,
                                                       const float* __restrict__ Wv,
                                                       const float* __restrict__ Wo) {
    extern __shared__ float sm[];
    float* bA = sm;
    float* bB = sm + 4160;   // 64*65
    float* bC = sm + 8320;
    int bh = blockIdx.x;
    int b = bh >> 4, h = bh & 15;
    int i0 = blockIdx.y * 128;
    int tid = threadIdx.x;
    const float* Gs = g_G + (size_t)bh * 4096;

    for (int i = tid; i < 4096; i += 256) {
        int r = i >> 6, c = i & 63;
        bA[r * 65 + c] = Gs[i];
        bB[r * 65 + c] = Wv[i];
    }
    __syncthreads();
    // T1 = G @ Wv^T -> bC
    for (int i = tid; i < 4096; i += 256) {
        int f = i >> 6, e = i & 63;
        float s = 0.f;
#pragma unroll 8
        for (int g = 0; g < 64; g++) s += bA[f * 65 + g] * bB[e * 65 + g];
        bC[f * 65 + e] = s;
    }
    __syncthreads();
    for (int i = tid; i < 4096; i += 256) {
        int r = i >> 6, c = i & 63;
        bA[r * 65 + c] = Wk[i];
    }
    __syncthreads();
    // T2 = Wk @ T1 -> bB
    for (int i = tid; i < 4096; i += 256) {
        int d = i >> 6, e = i & 63;
        float s = 0.f;
#pragma unroll 8
        for (int f = 0; f < 64; f++) s += bA[d * 65 + f] * bC[f * 65 + e];
        bB[d * 65 + e] = s;
    }
    __syncthreads();
    for (int i = tid; i < 4096; i += 256) {
        int r = i >> 6, c = i & 63;
        bC[r * 65 + c] = Wq[i];
    }
    __syncthreads();
    // M = Wq^T @ T2 / N -> bA
    for (int i = tid; i < 4096; i += 256) {
        int c = i >> 6, e = i & 63;
        float s = 0.f;
#pragma unroll 8
        for (int d = 0; d < 64; d++) s += bC[d * 65 + c] * bB[d * 65 + e];
        bA[c * 65 + e] = s * (1.0f / (float)Nq);
    }
    __syncthreads();
    // stage Wo chunk [128 rows i][64 e] flat at bB (spans bB..bC, 8192 floats)
    float* sWo = bB;
    for (int idx = tid; idx < 128 * 64; idx += 256) {
        int ii = idx >> 6, e = idx & 63;
        sWo[idx] = Wo[(size_t)(i0 + ii) * DIMq + h * DHq + e];
    }
    __syncthreads();
    // P[h*64+c, i0+ii] = sum_e M[c,e] * Wo[i0+ii, h*64+e]
    for (int idx = tid; idx < 64 * 128; idx += 256) {
        int c = idx >> 7, ii = idx & 127;
        float s = 0.f;
#pragma unroll 8
        for (int e = 0; e < 64; e++) s += bA[c * 65 + e] * sWo[ii * 64 + e];
        g_P[((size_t)b << 20) + (size_t)(h * DHq + c) * DIMq + (i0 + ii)] = s;
    }
}

// ============================================================
// Kernel 4: out[b] = x[b] @ P[b] + bo   (8192x1024x1024, 4 batches)
// 128x128x8 tiles, 256 thr, 8x8/thread as f32x2 pairs, reg prefetch
// ============================================================
#define BM 128
#define BN 128
#define BK 8
__global__ __launch_bounds__(256, 2) void gemm_kernel(const float* __restrict__ X,
                                                      const float* __restrict__ bo,
                                                      float* __restrict__ out) {
    __shared__ float As[BK][BM];
    __shared__ float Bs[BK][BN];
    int b = blockIdx.z;
    int m0 = blockIdx.y * BM;
    int n0 = blockIdx.x * BN;
    const float* A = X + (size_t)b * Nq * DIMq;
    const float* Bm = g_P + ((size_t)b << 20);
    int tid = threadIdx.x;
    int ty = tid >> 4, tx = tid & 15;
    int arow = tid >> 1, acol = (tid & 1) * 4;
    int brow = tid >> 5, bcol = (tid & 31) * 4;

    unsigned long long acc[8][4];
#pragma unroll
    for (int i = 0; i < 8; i++)
#pragma unroll
        for (int j = 0; j < 4; j++) acc[i][j] = 0ull;

    float4 aR = *(const float4*)(A + (size_t)(m0 + arow) * DIMq + acol);
    float4 bR = *(const float4*)(Bm + (size_t)brow * DIMq + n0 + bcol);

    for (int k0 = 0; k0 < DIMq; k0 += BK) {
        As[acol + 0][arow] = aR.x;
        As[acol + 1][arow] = aR.y;
        As[acol + 2][arow] = aR.z;
        As[acol + 3][arow] = aR.w;
        *(float4*)&Bs[brow][bcol] = bR;
        __syncthreads();
        if (k0 + BK < DIMq) {
            aR = *(const float4*)(A + (size_t)(m0 + arow) * DIMq + (k0 + BK) + acol);
            bR = *(const float4*)(Bm + (size_t)(k0 + BK + brow) * DIMq + n0 + bcol);
        }
#pragma unroll
        for (int kk = 0; kk < BK; kk++) {
            float4 a0 = *(const float4*)&As[kk][ty * 8];
            float4 a1 = *(const float4*)&As[kk][ty * 8 + 4];
            ulonglong2 b0 = *(const ulonglong2*)&Bs[kk][tx * 8];
            ulonglong2 b1 = *(const ulonglong2*)&Bs[kk][tx * 8 + 4];
            float av[8] = {a0.x, a0.y, a0.z, a0.w, a1.x, a1.y, a1.z, a1.w};
#pragma unroll
            for (int i = 0; i < 8; i++) {
                unsigned long long ap = pack2(av[i]);
                acc[i][0] = ffma2(ap, b0.x, acc[i][0]);
                acc[i][1] = ffma2(ap, b0.y, acc[i][1]);
                acc[i][2] = ffma2(ap, b1.x, acc[i][2]);
                acc[i][3] = ffma2(ap, b1.y, acc[i][3]);
            }
        }
        __syncthreads();
    }

    float bov[8];
#pragma unroll
    for (int j = 0; j < 8; j++) bov[j] = bo[n0 + tx * 8 + j];
#pragma unroll
    for (int i = 0; i < 8; i++) {
        float* orow = out + ((size_t)b * Nq + m0 + ty * 8 + i) * DIMq + n0 + tx * 8;
        float2 p0 = unpack2(acc[i][0]);
        float2 p1 = unpack2(acc[i][1]);
        float2 p2 = unpack2(acc[i][2]);
        float2 p3 = unpack2(acc[i][3]);
        float4 o0 = make_float4(p0.x + bov[0], p0.y + bov[1], p1.x + bov[2], p1.y + bov[3]);
        float4 o1 = make_float4(p2.x + bov[4], p2.y + bov[5], p3.x + bov[6], p3.y + bov[7]);
        *(float4*)orow = o0;
        *(float4*)(orow + 4) = o1;
    }
}

extern "C" void kernel_launch(void* const* d_in, const int* in_sizes, int n_in,
                              void* d_out, int out_size) {
    (void)in_sizes; (void)n_in; (void)out_size;
    const float* x  = (const float*)d_in[0];
    const float* Wq = (const float*)d_in[1];
    const float* Wk = (const float*)d_in[2];
    const float* Wv = (const float*)d_in[3];
    const float* Wo = (const float*)d_in[4];
    const float* bo = (const float*)d_in[5];
    float* out = (float*)d_out;

    gram_kernel<<<dim3(Bq * Hq, GSPLIT), 256>>>(x);
    reduceG_kernel<<<(Bq * Hq * DHq * DHq) / 256, 256>>>();
    cudaFuncSetAttribute(computeP_kernel, cudaFuncAttributeMaxDynamicSharedMemorySize, 49920);
    computeP_kernel<<<dim3(Bq * Hq, 8), 256, 49920>>>(Wq, Wk, Wv, Wo);
    gemm_kernel<<<dim3(DIMq / BN, Nq / BM, Bq), 256>>>(x, bo, out);
}

// round 3
// speedup vs baseline: 1.7168x; 1.7168x over previous
#include <cuda_runtime.h>
#include <cuda_bf16.h>
#include <cstdint>

#define Bq 4
#define Nq 8192
#define DIMq 1024
#define Hq 16
#define DHq 64
#define GSPLIT 16

// ---------------- device scratch (no allocation allowed) ----------------
__device__ float g_Gpart[GSPLIT][Bq * Hq * DHq * DHq];   // 16 MB
__device__ float g_G[Bq * Hq * DHq * DHq];               // 1 MB
__device__ __nv_bfloat16 g_Pthi[Bq * DIMq * DIMq];       // 8 MB  Pt[b][n][k]
__device__ __nv_bfloat16 g_Ptlo[Bq * DIMq * DIMq];       // 8 MB
__device__ __nv_bfloat16 g_xhi[Bq * Nq * DIMq];          // 64 MB
__device__ __nv_bfloat16 g_xlo[Bq * Nq * DIMq];          // 64 MB

// ---------------- PTX helpers ----------------
__device__ __forceinline__ uint32_t smem_u32(const void* p) {
    uint32_t a;
    asm("{ .reg .u64 t; cvta.to.shared.u64 t, %1; cvt.u32.u64 %0, t; }" : "=r"(a) : "l"(p));
    return a;
}

__device__ __forceinline__ void cpasync16(uint32_t saddr, const void* gptr) {
    asm volatile("cp.async.cg.shared.global [%0], [%1], 16;" :: "r"(saddr), "l"(gptr));
}
#define CP_COMMIT() asm volatile("cp.async.commit_group;" ::: "memory")
#define CP_WAIT(n)  asm volatile("cp.async.wait_group %0;" :: "n"(n) : "memory")

__device__ __forceinline__ void ldsm4(uint32_t* r, uint32_t addr) {
    asm volatile("ldmatrix.sync.aligned.m8n8.x4.shared.b16 {%0,%1,%2,%3}, [%4];"
                 : "=r"(r[0]), "=r"(r[1]), "=r"(r[2]), "=r"(r[3]) : "r"(addr));
}

__device__ __forceinline__ void mma16816(float* c, const uint32_t* a, const uint32_t* b) {
    asm volatile(
        "mma.sync.aligned.m16n8k16.row.col.f32.bf16.bf16.f32 "
        "{%0,%1,%2,%3}, {%4,%5,%6,%7}, {%8,%9}, {%0,%1,%2,%3};"
        : "+f"(c[0]), "+f"(c[1]), "+f"(c[2]), "+f"(c[3])
        : "r"(a[0]), "r"(a[1]), "r"(a[2]), "r"(a[3]), "r"(b[0]), "r"(b[1]));
}

// ---- packed f32x2 helpers for gram kernel ----
__device__ __forceinline__ unsigned long long pack2(float x) {
    unsigned long long v; unsigned u = __float_as_uint(x);
    asm("mov.b64 %0, {%1, %2};" : "=l"(v) : "r"(u), "r"(u));
    return v;
}
__device__ __forceinline__ unsigned long long ffma2(unsigned long long a,
                                                    unsigned long long b,
                                                    unsigned long long c) {
    unsigned long long d;
    asm("fma.rn.f32x2 %0, %1, %2, %3;" : "=l"(d) : "l"(a), "l"(b), "l"(c));
    return d;
}
__device__ __forceinline__ float2 unpack2(unsigned long long v) {
    unsigned lo, hi;
    asm("mov.b64 {%0, %1}, %2;" : "=r"(lo), "=r"(hi) : "l"(v));
    return make_float2(__uint_as_float(lo), __uint_as_float(hi));
}

// ============================================================
// Kernel 0: split x -> bf16 hi/lo
// ============================================================
__global__ __launch_bounds__(256) void convert_x_kernel(const float* __restrict__ x) {
    size_t i = ((size_t)blockIdx.x * 256 + threadIdx.x) * 4;
    float4 v = *(const float4*)(x + i);
    __nv_bfloat16 h0 = __float2bfloat16(v.x);
    __nv_bfloat16 h1 = __float2bfloat16(v.y);
    __nv_bfloat16 h2 = __float2bfloat16(v.z);
    __nv_bfloat16 h3 = __float2bfloat16(v.w);
    __nv_bfloat16 l0 = __float2bfloat16(v.x - __bfloat162float(h0));
    __nv_bfloat16 l1 = __float2bfloat16(v.y - __bfloat162float(h1));
    __nv_bfloat16 l2 = __float2bfloat16(v.z - __bfloat162float(h2));
    __nv_bfloat16 l3 = __float2bfloat16(v.w - __bfloat162float(h3));
    ushort4 hv = make_ushort4(__bfloat16_as_ushort(h0), __bfloat16_as_ushort(h1),
                              __bfloat16_as_ushort(h2), __bfloat16_as_ushort(h3));
    ushort4 lv = make_ushort4(__bfloat16_as_ushort(l0), __bfloat16_as_ushort(l1),
                              __bfloat16_as_ushort(l2), __bfloat16_as_ushort(l3));
    *(ushort4*)((unsigned short*)g_xhi + i) = hv;
    *(ushort4*)((unsigned short*)g_xlo + i) = lv;
}

// ============================================================
// Kernel 1: per-(b,h) Gram G = x_h^T x_h, split over N (FFMA2)
// ============================================================
__global__ __launch_bounds__(256) void gram_kernel(const float* __restrict__ x) {
    int bh = blockIdx.x;
    int sp = blockIdx.y;
    int b = bh >> 4, h = bh & 15;
    __shared__ float sx[8][64];
    int tid = threadIdx.x;
    int ty = tid >> 4, tx = tid & 15;
    int lr = tid >> 5, lc = (tid & 31) * 2;

    unsigned long long acc[4][2];
#pragma unroll
    for (int i = 0; i < 4; i++) { acc[i][0] = 0ull; acc[i][1] = 0ull; }

    const float* xb = x + ((size_t)b * Nq + (size_t)sp * (Nq / GSPLIT)) * DIMq + h * DHq;
    const int ITERS = (Nq / GSPLIT) / 8;

    for (int it = 0; it < ITERS; ++it) {
        *(float2*)&sx[lr][lc] = *(const float2*)(xb + (size_t)(it * 8 + lr) * DIMq + lc);
        __syncthreads();
#pragma unroll
        for (int r = 0; r < 8; r++) {
            float4 a4 = *(const float4*)&sx[r][ty * 4];
            ulonglong2 b2 = *(const ulonglong2*)&sx[r][tx * 4];
            unsigned long long ap;
            ap = pack2(a4.x); acc[0][0] = ffma2(ap, b2.x, acc[0][0]); acc[0][1] = ffma2(ap, b2.y, acc[0][1]);
            ap = pack2(a4.y); acc[1][0] = ffma2(ap, b2.x, acc[1][0]); acc[1][1] = ffma2(ap, b2.y, acc[1][1]);
            ap = pack2(a4.z); acc[2][0] = ffma2(ap, b2.x, acc[2][0]); acc[2][1] = ffma2(ap, b2.y, acc[2][1]);
            ap = pack2(a4.w); acc[3][0] = ffma2(ap, b2.x, acc[3][0]); acc[3][1] = ffma2(ap, b2.y, acc[3][1]);
        }
        __syncthreads();
    }

    float* dst = g_Gpart[sp] + (size_t)bh * 4096;
#pragma unroll
    for (int i = 0; i < 4; i++) {
        int row = ty * 4 + i;
        float2 v0 = unpack2(acc[i][0]);
        float2 v1 = unpack2(acc[i][1]);
        dst[row * 64 + tx * 4 + 0] = v0.x;
        dst[row * 64 + tx * 4 + 1] = v0.y;
        dst[row * 64 + tx * 4 + 2] = v1.x;
        dst[row * 64 + tx * 4 + 3] = v1.y;
    }
}

__global__ void reduceG_kernel() {
    int idx = blockIdx.x * 256 + threadIdx.x;
    float s = 0.f;
#pragma unroll
    for (int p = 0; p < GSPLIT; p++) s += g_Gpart[p][idx];
    g_G[idx] = s;
}

// ============================================================
// Kernel 3: Pt[b][n][k] (bf16 hi/lo) = (Wq^T Wk G Wv^T / N) chained with Wo
// ============================================================
__global__ __launch_bounds__(256) void computeP_kernel(const float* __restrict__ Wq,
                                                       const float* __restrict__ Wk,
                                                       const float* __restrict__ Wv,
                                                       const float* __restrict__ Wo) {
    extern __shared__ float sm[];
    float* bA = sm;
    float* bB = sm + 4160;
    float* bC = sm + 8320;
    int bh = blockIdx.x;
    int b = bh >> 4, h = bh & 15;
    int i0 = blockIdx.y * 128;
    int tid = threadIdx.x;
    const float* Gs = g_G + (size_t)bh * 4096;

    for (int i = tid; i < 4096; i += 256) {
        int r = i >> 6, c = i & 63;
        bA[r * 65 + c] = Gs[i];
        bB[r * 65 + c] = Wv[i];
    }
    __syncthreads();
    for (int i = tid; i < 4096; i += 256) {
        int f = i >> 6, e = i & 63;
        float s = 0.f;
#pragma unroll 8
        for (int g = 0; g < 64; g++) s += bA[f * 65 + g] * bB[e * 65 + g];
        bC[f * 65 + e] = s;
    }
    __syncthreads();
    for (int i = tid; i < 4096; i += 256) {
        int r = i >> 6, c = i & 63;
        bA[r * 65 + c] = Wk[i];
    }
    __syncthreads();
    for (int i = tid; i < 4096; i += 256) {
        int d = i >> 6, e = i & 63;
        float s = 0.f;
#pragma unroll 8
        for (int f = 0; f < 64; f++) s += bA[d * 65 + f] * bC[f * 65 + e];
        bB[d * 65 + e] = s;
    }
    __syncthreads();
    for (int i = tid; i < 4096; i += 256) {
        int r = i >> 6, c = i & 63;
        bC[r * 65 + c] = Wq[i];
    }
    __syncthreads();
    for (int i = tid; i < 4096; i += 256) {
        int c = i >> 6, e = i & 63;
        float s = 0.f;
#pragma unroll 8
        for (int d = 0; d < 64; d++) s += bC[d * 65 + c] * bB[d * 65 + e];
        bA[c * 65 + e] = s * (1.0f / (float)Nq);
    }
    __syncthreads();
    float* sWo = bB;
    for (int idx = tid; idx < 128 * 64; idx += 256) {
        int ii = idx >> 6, e = idx & 63;
        sWo[idx] = Wo[(size_t)(i0 + ii) * DIMq + h * DHq + e];
    }
    __syncthreads();
    for (int idx = tid; idx < 64 * 128; idx += 256) {
        int c = idx >> 7, ii = idx & 127;
        float s = 0.f;
#pragma unroll 8
        for (int e = 0; e < 64; e++) s += bA[c * 65 + e] * sWo[ii * 64 + e];
        size_t o = ((size_t)b << 20) + (size_t)(i0 + ii) * DIMq + (h * DHq + c);
        __nv_bfloat16 hi = __float2bfloat16(s);
        g_Pthi[o] = hi;
        g_Ptlo[o] = __float2bfloat16(s - __bfloat162float(hi));
    }
}

// ============================================================
// Kernel 4: HMMA GEMM  out[b] = x[b] @ P[b] + bo
// CTA 128x128, K-chunk 32, 3-stage cp.async, 3-term bf16 split
// ============================================================
#define STAGE_BYTES 32768
#define NSTAGES 3
#define KCHUNKS 32

__device__ __forceinline__ void issue_chunk(uint32_t sbase, const char* gAh,
                                            const char* gAl, const char* gBh,
                                            const char* gBl, int tid) {
#pragma unroll
    for (int j = 0; j < 2; j++) {
        int idx = j * 256 + tid;
        int row = idx >> 2, g = idx & 3;
        uint32_t so = row * 64 + (((g ^ ((row >> 1) & 3))) << 4);
        size_t go = (size_t)row * 2048 + g * 16;
        cpasync16(sbase + so, gAh + go);
        cpasync16(sbase + 8192 + so, gAl + go);
        cpasync16(sbase + 16384 + so, gBh + go);
        cpasync16(sbase + 24576 + so, gBl + go);
    }
}

__global__ __launch_bounds__(256) void gemm_hmma_kernel(const float* __restrict__ bo,
                                                        float* __restrict__ out) {
    extern __shared__ __align__(128) char dsm[];
    uint32_t sbase = smem_u32(dsm);

    int tid = threadIdx.x;
    int warp = tid >> 5, lane = tid & 31;
    int wm = warp & 3;   // m offset 32*wm
    int wn = warp >> 2;  // n offset 64*wn
    int b = blockIdx.z;
    int m0 = blockIdx.y * 128;
    int n0 = blockIdx.x * 128;

    const char* gAh = (const char*)g_xhi + (((size_t)b * Nq + m0) * DIMq) * 2;
    const char* gAl = (const char*)g_xlo + (((size_t)b * Nq + m0) * DIMq) * 2;
    const char* gBh = (const char*)g_Pthi + (((size_t)b * DIMq + n0) * DIMq) * 2;
    const char* gBl = (const char*)g_Ptlo + (((size_t)b * DIMq + n0) * DIMq) * 2;

    float acc[2][8][4];
#pragma unroll
    for (int mt = 0; mt < 2; mt++)
#pragma unroll
        for (int j = 0; j < 8; j++)
#pragma unroll
            for (int q = 0; q < 4; q++) acc[mt][j][q] = 0.f;

    // ldmatrix address components (per lane)
    int rowA = wm * 32 + (lane & 15);              // + mt*16
    int gA = (lane >> 4);                          // + 2s
    int rowB = wn * 64 + ((lane >> 4) & 1) * 8 + (lane & 7);  // + jt*16
    int gB = ((lane >> 3) & 1);                    // + 2s

    // prologue: 2 chunks in flight
    issue_chunk(sbase + 0 * STAGE_BYTES, gAh, gAl, gBh, gBl, tid);
    CP_COMMIT();
    issue_chunk(sbase + 1 * STAGE_BYTES, gAh + 64, gAl + 64, gBh + 64, gBl + 64, tid);
    CP_COMMIT();

#pragma unroll 1
    for (int ki = 0; ki < KCHUNKS; ki++) {
        CP_WAIT(1);
        __syncthreads();
        if (ki + 2 < KCHUNKS) {
            int slot = (ki + 2) % NSTAGES;
            size_t off = (size_t)(ki + 2) * 64;
            issue_chunk(sbase + slot * STAGE_BYTES, gAh + off, gAl + off, gBh + off, gBl + off, tid);
        }
        CP_COMMIT();

        uint32_t st = sbase + (ki % NSTAGES) * STAGE_BYTES;
#pragma unroll
        for (int s = 0; s < 2; s++) {
            uint32_t ah[2][4], al[2][4], bh[8][2], bl[8][2];
#pragma unroll
            for (int mt = 0; mt < 2; mt++) {
                int r = rowA + mt * 16;
                int gg = ((gA + 2 * s) ^ ((r >> 1) & 3)) << 4;
                uint32_t ad = st + r * 64 + gg;
                ldsm4(ah[mt], ad);
                ldsm4(al[mt], ad + 8192);
            }
#pragma unroll
            for (int jt = 0; jt < 4; jt++) {
                int r = rowB + jt * 16;
                int gg = ((gB + 2 * s) ^ ((r >> 1) & 3)) << 4;
                uint32_t ad = st + 16384 + r * 64 + gg;
                uint32_t t0[4], t1[4];
                ldsm4(t0, ad);
                ldsm4(t1, ad + 8192);
                bh[jt * 2][0] = t0[0]; bh[jt * 2][1] = t0[1];
                bh[jt * 2 + 1][0] = t0[2]; bh[jt * 2 + 1][1] = t0[3];
                bl[jt * 2][0] = t1[0]; bl[jt * 2][1] = t1[1];
                bl[jt * 2 + 1][0] = t1[2]; bl[jt * 2 + 1][1] = t1[3];
            }
#pragma unroll
            for (int mt = 0; mt < 2; mt++) {
#pragma unroll
                for (int j = 0; j < 8; j++) {
                    mma16816(acc[mt][j], ah[mt], bh[j]);
                    mma16816(acc[mt][j], ah[mt], bl[j]);
                    mma16816(acc[mt][j], al[mt], bh[j]);
                }
            }
        }
        __syncthreads();
    }

    // epilogue: direct stores + bias
    int r0 = lane >> 2, cpair = (lane & 3) * 2;
#pragma unroll
    for (int j = 0; j < 8; j++) {
        int n = n0 + wn * 64 + j * 8 + cpair;
        float2 bb = *(const float2*)(bo + n);
#pragma unroll
        for (int mt = 0; mt < 2; mt++) {
            int m = m0 + wm * 32 + mt * 16 + r0;
            float2 o0 = make_float2(acc[mt][j][0] + bb.x, acc[mt][j][1] + bb.y);
            float2 o1 = make_float2(acc[mt][j][2] + bb.x, acc[mt][j][3] + bb.y);
            *(float2*)(out + ((size_t)b * Nq + m) * DIMq + n) = o0;
            *(float2*)(out + ((size_t)b * Nq + m + 8) * DIMq + n) = o1;
        }
    }
}

// ============================================================
extern "C" void kernel_launch(void* const* d_in, const int* in_sizes, int n_in,
                              void* d_out, int out_size) {
    (void)in_sizes; (void)n_in; (void)out_size;
    const float* x  = (const float*)d_in[0];
    const float* Wq = (const float*)d_in[1];
    const float* Wk = (const float*)d_in[2];
    const float* Wv = (const float*)d_in[3];
    const float* Wo = (const float*)d_in[4];
    const float* bo = (const float*)d_in[5];
    float* out = (float*)d_out;

    convert_x_kernel<<<(Bq * Nq * DIMq) / 4 / 256, 256>>>(x);
    gram_kernel<<<dim3(Bq * Hq, GSPLIT), 256>>>(x);
    reduceG_kernel<<<(Bq * Hq * DHq * DHq) / 256, 256>>>();
    cudaFuncSetAttribute(computeP_kernel, cudaFuncAttributeMaxDynamicSharedMemorySize, 49920);
    computeP_kernel<<<dim3(Bq * Hq, 8), 256, 49920>>>(Wq, Wk, Wv, Wo);
    cudaFuncSetAttribute(gemm_hmma_kernel, cudaFuncAttributeMaxDynamicSharedMemorySize,
                         NSTAGES * STAGE_BYTES);
    gemm_hmma_kernel<<<dim3(DIMq / 128, Nq / 128, Bq), 256, NSTAGES * STAGE_BYTES>>>(bo, out);
}

// round 4
// speedup vs baseline: 2.5197x; 1.4677x over previous
#include <cuda_runtime.h>
#include <cuda_bf16.h>
#include <cstdint>

#define Bq 4
#define Nq 8192
#define DIMq 1024
#define Hq 16
#define DHq 64
#define GSPLIT 16

// ---------------- device scratch (no allocation allowed) ----------------
__device__ float g_Gpart[GSPLIT][Bq * Hq * DHq * DHq];   // 16 MB
__device__ float g_G[Bq * Hq * DHq * DHq];               // 1 MB
__device__ float g_M[Bq * Hq * DHq * DHq];               // 1 MB
__device__ __nv_bfloat16 g_Pthi[Bq * DIMq * DIMq];       // 8 MB  Pt[b][n][k]
__device__ __nv_bfloat16 g_Ptlo[Bq * DIMq * DIMq];       // 8 MB
__device__ __nv_bfloat16 g_xhi[Bq * Nq * DIMq];          // 64 MB
__device__ __nv_bfloat16 g_xlo[Bq * Nq * DIMq];          // 64 MB

// ---------------- PTX helpers ----------------
__device__ __forceinline__ uint32_t smem_u32(const void* p) {
    uint32_t a;
    asm("{ .reg .u64 t; cvta.to.shared.u64 t, %1; cvt.u32.u64 %0, t; }" : "=r"(a) : "l"(p));
    return a;
}

__device__ __forceinline__ void cpasync16(uint32_t saddr, const void* gptr) {
    asm volatile("cp.async.cg.shared.global [%0], [%1], 16;" :: "r"(saddr), "l"(gptr));
}
#define CP_COMMIT() asm volatile("cp.async.commit_group;" ::: "memory")
#define CP_WAIT(n)  asm volatile("cp.async.wait_group %0;" :: "n"(n) : "memory")

__device__ __forceinline__ void ldsm4(uint32_t* r, uint32_t addr) {
    asm volatile("ldmatrix.sync.aligned.m8n8.x4.shared.b16 {%0,%1,%2,%3}, [%4];"
                 : "=r"(r[0]), "=r"(r[1]), "=r"(r[2]), "=r"(r[3]) : "r"(addr));
}

__device__ __forceinline__ void mma16816(float* c, const uint32_t* a, const uint32_t* b) {
    asm volatile(
        "mma.sync.aligned.m16n8k16.row.col.f32.bf16.bf16.f32 "
        "{%0,%1,%2,%3}, {%4,%5,%6,%7}, {%8,%9}, {%0,%1,%2,%3};"
        : "+f"(c[0]), "+f"(c[1]), "+f"(c[2]), "+f"(c[3])
        : "r"(a[0]), "r"(a[1]), "r"(a[2]), "r"(a[3]), "r"(b[0]), "r"(b[1]));
}

// ---- packed f32x2 helpers for gram kernel ----
__device__ __forceinline__ unsigned long long pack2(float x) {
    unsigned long long v; unsigned u = __float_as_uint(x);
    asm("mov.b64 %0, {%1, %2};" : "=l"(v) : "r"(u), "r"(u));
    return v;
}
__device__ __forceinline__ unsigned long long ffma2(unsigned long long a,
                                                    unsigned long long b,
                                                    unsigned long long c) {
    unsigned long long d;
    asm("fma.rn.f32x2 %0, %1, %2, %3;" : "=l"(d) : "l"(a), "l"(b), "l"(c));
    return d;
}
__device__ __forceinline__ float2 unpack2(unsigned long long v) {
    unsigned lo, hi;
    asm("mov.b64 {%0, %1}, %2;" : "=r"(lo), "=r"(hi) : "l"(v));
    return make_float2(__uint_as_float(lo), __uint_as_float(hi));
}

// ============================================================
// Kernel 0: split x -> bf16 hi/lo
// ============================================================
__global__ __launch_bounds__(256) void convert_x_kernel(const float* __restrict__ x) {
    size_t i = ((size_t)blockIdx.x * 256 + threadIdx.x) * 4;
    float4 v = *(const float4*)(x + i);
    __nv_bfloat16 h0 = __float2bfloat16(v.x);
    __nv_bfloat16 h1 = __float2bfloat16(v.y);
    __nv_bfloat16 h2 = __float2bfloat16(v.z);
    __nv_bfloat16 h3 = __float2bfloat16(v.w);
    __nv_bfloat16 l0 = __float2bfloat16(v.x - __bfloat162float(h0));
    __nv_bfloat16 l1 = __float2bfloat16(v.y - __bfloat162float(h1));
    __nv_bfloat16 l2 = __float2bfloat16(v.z - __bfloat162float(h2));
    __nv_bfloat16 l3 = __float2bfloat16(v.w - __bfloat162float(h3));
    ushort4 hv = make_ushort4(__bfloat16_as_ushort(h0), __bfloat16_as_ushort(h1),
                              __bfloat16_as_ushort(h2), __bfloat16_as_ushort(h3));
    ushort4 lv = make_ushort4(__bfloat16_as_ushort(l0), __bfloat16_as_ushort(l1),
                              __bfloat16_as_ushort(l2), __bfloat16_as_ushort(l3));
    *(ushort4*)((unsigned short*)g_xhi + i) = hv;
    *(ushort4*)((unsigned short*)g_xlo + i) = lv;
}

// ============================================================
// Kernel 1: per-(b,h) Gram G = x_h^T x_h, split over N (FFMA2)
// ============================================================
__global__ __launch_bounds__(256) void gram_kernel(const float* __restrict__ x) {
    int bh = blockIdx.x;
    int sp = blockIdx.y;
    int b = bh >> 4, h = bh & 15;
    __shared__ float sx[8][64];
    int tid = threadIdx.x;
    int ty = tid >> 4, tx = tid & 15;
    int lr = tid >> 5, lc = (tid & 31) * 2;

    unsigned long long acc[4][2];
#pragma unroll
    for (int i = 0; i < 4; i++) { acc[i][0] = 0ull; acc[i][1] = 0ull; }

    const float* xb = x + ((size_t)b * Nq + (size_t)sp * (Nq / GSPLIT)) * DIMq + h * DHq;
    const int ITERS = (Nq / GSPLIT) / 8;

    for (int it = 0; it < ITERS; ++it) {
        *(float2*)&sx[lr][lc] = *(const float2*)(xb + (size_t)(it * 8 + lr) * DIMq + lc);
        __syncthreads();
#pragma unroll
        for (int r = 0; r < 8; r++) {
            float4 a4 = *(const float4*)&sx[r][ty * 4];
            ulonglong2 b2 = *(const ulonglong2*)&sx[r][tx * 4];
            unsigned long long ap;
            ap = pack2(a4.x); acc[0][0] = ffma2(ap, b2.x, acc[0][0]); acc[0][1] = ffma2(ap, b2.y, acc[0][1]);
            ap = pack2(a4.y); acc[1][0] = ffma2(ap, b2.x, acc[1][0]); acc[1][1] = ffma2(ap, b2.y, acc[1][1]);
            ap = pack2(a4.z); acc[2][0] = ffma2(ap, b2.x, acc[2][0]); acc[2][1] = ffma2(ap, b2.y, acc[2][1]);
            ap = pack2(a4.w); acc[3][0] = ffma2(ap, b2.x, acc[3][0]); acc[3][1] = ffma2(ap, b2.y, acc[3][1]);
        }
        __syncthreads();
    }

    float* dst = g_Gpart[sp] + (size_t)bh * 4096;
#pragma unroll
    for (int i = 0; i < 4; i++) {
        int row = ty * 4 + i;
        float2 v0 = unpack2(acc[i][0]);
        float2 v1 = unpack2(acc[i][1]);
        dst[row * 64 + tx * 4 + 0] = v0.x;
        dst[row * 64 + tx * 4 + 1] = v0.y;
        dst[row * 64 + tx * 4 + 2] = v1.x;
        dst[row * 64 + tx * 4 + 3] = v1.y;
    }
}

__global__ void reduceG_kernel() {
    int idx = blockIdx.x * 256 + threadIdx.x;
    float s = 0.f;
#pragma unroll
    for (int p = 0; p < GSPLIT; p++) s += g_Gpart[p][idx];
    g_G[idx] = s;
}

// ============================================================
// Kernel 2b: M = Wq^T Wk G Wv^T / N, ONE block per (b,h)
// 4x4 register tiles, stride-65 padded smem
// ============================================================
__global__ __launch_bounds__(256) void computeM_kernel(const float* __restrict__ Wq,
                                                       const float* __restrict__ Wk,
                                                       const float* __restrict__ Wv) {
    __shared__ float sA[64 * 65 / 4 * 4];  // 64x65
    __shared__ float sB[64 * 65];
    __shared__ float sC[64 * 65];
    int bh = blockIdx.x;
    int tid = threadIdx.x;
    int ty = tid >> 4, tx = tid & 15;
    const float* Gs = g_G + (size_t)bh * 4096;

    for (int i = tid; i < 4096; i += 256) {
        int r = i >> 6, c = i & 63;
        sA[r * 65 + c] = Gs[i];
        sB[r * 65 + c] = Wv[i];
    }
    __syncthreads();

    float acc[4][4];
    // Phase 1: T1[f][e] = sum_g G[f][g] * Wv[e][g]  -> sC
#pragma unroll
    for (int i = 0; i < 4; i++)
#pragma unroll
        for (int j = 0; j < 4; j++) acc[i][j] = 0.f;
#pragma unroll 4
    for (int g = 0; g < 64; g++) {
        float a[4], bb[4];
#pragma unroll
        for (int i = 0; i < 4; i++) a[i] = sA[(ty * 4 + i) * 65 + g];
#pragma unroll
        for (int j = 0; j < 4; j++) bb[j] = sB[(tx * 4 + j) * 65 + g];
#pragma unroll
        for (int i = 0; i < 4; i++)
#pragma unroll
            for (int j = 0; j < 4; j++) acc[i][j] += a[i] * bb[j];
    }
    __syncthreads();
#pragma unroll
    for (int i = 0; i < 4; i++)
#pragma unroll
        for (int j = 0; j < 4; j++) sC[(ty * 4 + i) * 65 + tx * 4 + j] = acc[i][j];
    for (int i = tid; i < 4096; i += 256) {
        int r = i >> 6, c = i & 63;
        sA[r * 65 + c] = Wk[i];
    }
    __syncthreads();

    // Phase 2: T2[d][e] = sum_f Wk[d][f] * T1[f][e] -> sB
#pragma unroll
    for (int i = 0; i < 4; i++)
#pragma unroll
        for (int j = 0; j < 4; j++) acc[i][j] = 0.f;
#pragma unroll 4
    for (int f = 0; f < 64; f++) {
        float a[4], bb[4];
#pragma unroll
        for (int i = 0; i < 4; i++) a[i] = sA[(ty * 4 + i) * 65 + f];
#pragma unroll
        for (int j = 0; j < 4; j++) bb[j] = sC[f * 65 + tx * 4 + j];
#pragma unroll
        for (int i = 0; i < 4; i++)
#pragma unroll
            for (int j = 0; j < 4; j++) acc[i][j] += a[i] * bb[j];
    }
    __syncthreads();
#pragma unroll
    for (int i = 0; i < 4; i++)
#pragma unroll
        for (int j = 0; j < 4; j++) sB[(ty * 4 + i) * 65 + tx * 4 + j] = acc[i][j];
    for (int i = tid; i < 4096; i += 256) {
        int r = i >> 6, c = i & 63;
        sA[r * 65 + c] = Wq[i];
    }
    __syncthreads();

    // Phase 3: M[c][e] = (1/N) sum_d Wq[d][c] * T2[d][e]
#pragma unroll
    for (int i = 0; i < 4; i++)
#pragma unroll
        for (int j = 0; j < 4; j++) acc[i][j] = 0.f;
#pragma unroll 4
    for (int d = 0; d < 64; d++) {
        float a[4], bb[4];
#pragma unroll
        for (int i = 0; i < 4; i++) a[i] = sA[d * 65 + ty * 4 + i];
#pragma unroll
        for (int j = 0; j < 4; j++) bb[j] = sB[d * 65 + tx * 4 + j];
#pragma unroll
        for (int i = 0; i < 4; i++)
#pragma unroll
            for (int j = 0; j < 4; j++) acc[i][j] += a[i] * bb[j];
    }
    const float sc = 1.0f / (float)Nq;
    float* Ms = g_M + (size_t)bh * 4096;
#pragma unroll
    for (int i = 0; i < 4; i++)
#pragma unroll
        for (int j = 0; j < 4; j++)
            Ms[(ty * 4 + i) * 64 + tx * 4 + j] = acc[i][j] * sc;
}

// ============================================================
// Kernel 3: expand Pt[b][i][h*64+c] = sum_e M[bh][c][e] * Wo[i][h*64+e]
// 4x8 register tiles; dyn smem 49920 B
// ============================================================
__global__ __launch_bounds__(256) void expandP_kernel(const float* __restrict__ Wo) {
    extern __shared__ float esm[];
    float* sM = esm;            // [c][e] stride 65  (16640 B)
    float* sW = esm + 4160;     // [ii][e] stride 65 (33280 B)
    int bh = blockIdx.x;
    int b = bh >> 4, h = bh & 15;
    int i0 = blockIdx.y * 128;
    int tid = threadIdx.x;
    const float* Ms = g_M + (size_t)bh * 4096;

    for (int i = tid; i < 4096; i += 256) {
        int r = i >> 6, c = i & 63;
        sM[r * 65 + c] = Ms[i];
    }
    for (int idx = tid; idx < 128 * 64; idx += 256) {
        int ii = idx >> 6, e = idx & 63;
        sW[ii * 65 + e] = Wo[(size_t)(i0 + ii) * DIMq + h * DHq + e];
    }
    __syncthreads();

    int ti = tid >> 3;  // 0..31 -> rows ii = ti*4..+3
    int tc = tid & 7;   // cols c = tc*8..+7
    float acc[4][8];
#pragma unroll
    for (int i = 0; i < 4; i++)
#pragma unroll
        for (int j = 0; j < 8; j++) acc[i][j] = 0.f;

#pragma unroll 4
    for (int e = 0; e < 64; e++) {
        float w[4], m[8];
#pragma unroll
        for (int i = 0; i < 4; i++) w[i] = sW[(ti * 4 + i) * 65 + e];
#pragma unroll
        for (int j = 0; j < 8; j++) m[j] = sM[(tc * 8 + j) * 65 + e];
#pragma unroll
        for (int i = 0; i < 4; i++)
#pragma unroll
            for (int j = 0; j < 8; j++) acc[i][j] += w[i] * m[j];
    }

#pragma unroll
    for (int i = 0; i < 4; i++) {
        int ii = i0 + ti * 4 + i;
#pragma unroll
        for (int j = 0; j < 8; j++) {
            float v = acc[i][j];
            size_t o = ((size_t)b << 20) + (size_t)ii * DIMq + (h * DHq + tc * 8 + j);
            __nv_bfloat16 hi = __float2bfloat16(v);
            g_Pthi[o] = hi;
            g_Ptlo[o] = __float2bfloat16(v - __bfloat162float(hi));
        }
    }
}

// ============================================================
// Kernel 4: HMMA GEMM  out[b] = x[b] @ P[b] + bo
// CTA 128x128, K-chunk 32, 3-stage cp.async, 3-term bf16 split
// ============================================================
#define STAGE_BYTES 32768
#define NSTAGES 3
#define KCHUNKS 32

__device__ __forceinline__ void issue_chunk(uint32_t sbase, const char* gAh,
                                            const char* gAl, const char* gBh,
                                            const char* gBl, int tid) {
#pragma unroll
    for (int j = 0; j < 2; j++) {
        int idx = j * 256 + tid;
        int row = idx >> 2, g = idx & 3;
        uint32_t so = row * 64 + (((g ^ ((row >> 1) & 3))) << 4);
        size_t go = (size_t)row * 2048 + g * 16;
        cpasync16(sbase + so, gAh + go);
        cpasync16(sbase + 8192 + so, gAl + go);
        cpasync16(sbase + 16384 + so, gBh + go);
        cpasync16(sbase + 24576 + so, gBl + go);
    }
}

__global__ __launch_bounds__(256) void gemm_hmma_kernel(const float* __restrict__ bo,
                                                        float* __restrict__ out) {
    extern __shared__ __align__(128) char dsm[];
    uint32_t sbase = smem_u32(dsm);

    int tid = threadIdx.x;
    int warp = tid >> 5, lane = tid & 31;
    int wm = warp & 3;
    int wn = warp >> 2;
    int b = blockIdx.z;
    int m0 = blockIdx.y * 128;
    int n0 = blockIdx.x * 128;

    const char* gAh = (const char*)g_xhi + (((size_t)b * Nq + m0) * DIMq) * 2;
    const char* gAl = (const char*)g_xlo + (((size_t)b * Nq + m0) * DIMq) * 2;
    const char* gBh = (const char*)g_Pthi + (((size_t)b * DIMq + n0) * DIMq) * 2;
    const char* gBl = (const char*)g_Ptlo + (((size_t)b * DIMq + n0) * DIMq) * 2;

    float acc[2][8][4];
#pragma unroll
    for (int mt = 0; mt < 2; mt++)
#pragma unroll
        for (int j = 0; j < 8; j++)
#pragma unroll
            for (int q = 0; q < 4; q++) acc[mt][j][q] = 0.f;

    int rowA = wm * 32 + (lane & 15);
    int gA = (lane >> 4);
    int rowB = wn * 64 + ((lane >> 4) & 1) * 8 + (lane & 7);
    int gB = ((lane >> 3) & 1);

    issue_chunk(sbase + 0 * STAGE_BYTES, gAh, gAl, gBh, gBl, tid);
    CP_COMMIT();
    issue_chunk(sbase + 1 * STAGE_BYTES, gAh + 64, gAl + 64, gBh + 64, gBl + 64, tid);
    CP_COMMIT();

#pragma unroll 1
    for (int ki = 0; ki < KCHUNKS; ki++) {
        CP_WAIT(1);
        __syncthreads();
        if (ki + 2 < KCHUNKS) {
            int slot = (ki + 2) % NSTAGES;
            size_t off = (size_t)(ki + 2) * 64;
            issue_chunk(sbase + slot * STAGE_BYTES, gAh + off, gAl + off, gBh + off, gBl + off, tid);
        }
        CP_COMMIT();

        uint32_t st = sbase + (ki % NSTAGES) * STAGE_BYTES;
#pragma unroll
        for (int s = 0; s < 2; s++) {
            uint32_t ah[2][4], al[2][4], bh[8][2], bl[8][2];
#pragma unroll
            for (int mt = 0; mt < 2; mt++) {
                int r = rowA + mt * 16;
                int gg = ((gA + 2 * s) ^ ((r >> 1) & 3)) << 4;
                uint32_t ad = st + r * 64 + gg;
                ldsm4(ah[mt], ad);
                ldsm4(al[mt], ad + 8192);
            }
#pragma unroll
            for (int jt = 0; jt < 4; jt++) {
                int r = rowB + jt * 16;
                int gg = ((gB + 2 * s) ^ ((r >> 1) & 3)) << 4;
                uint32_t ad = st + 16384 + r * 64 + gg;
                uint32_t t0[4], t1[4];
                ldsm4(t0, ad);
                ldsm4(t1, ad + 8192);
                bh[jt * 2][0] = t0[0]; bh[jt * 2][1] = t0[1];
                bh[jt * 2 + 1][0] = t0[2]; bh[jt * 2 + 1][1] = t0[3];
                bl[jt * 2][0] = t1[0]; bl[jt * 2][1] = t1[1];
                bl[jt * 2 + 1][0] = t1[2]; bl[jt * 2 + 1][1] = t1[3];
            }
#pragma unroll
            for (int mt = 0; mt < 2; mt++) {
#pragma unroll
                for (int j = 0; j < 8; j++) {
                    mma16816(acc[mt][j], ah[mt], bh[j]);
                    mma16816(acc[mt][j], ah[mt], bl[j]);
                    mma16816(acc[mt][j], al[mt], bh[j]);
                }
            }
        }
        __syncthreads();
    }

    int r0 = lane >> 2, cpair = (lane & 3) * 2;
#pragma unroll
    for (int j = 0; j < 8; j++) {
        int n = n0 + wn * 64 + j * 8 + cpair;
        float2 bb = *(const float2*)(bo + n);
#pragma unroll
        for (int mt = 0; mt < 2; mt++) {
            int m = m0 + wm * 32 + mt * 16 + r0;
            float2 o0 = make_float2(acc[mt][j][0] + bb.x, acc[mt][j][1] + bb.y);
            float2 o1 = make_float2(acc[mt][j][2] + bb.x, acc[mt][j][3] + bb.y);
            *(float2*)(out + ((size_t)b * Nq + m) * DIMq + n) = o0;
            *(float2*)(out + ((size_t)b * Nq + m + 8) * DIMq + n) = o1;
        }
    }
}

// ============================================================
extern "C" void kernel_launch(void* const* d_in, const int* in_sizes, int n_in,
                              void* d_out, int out_size) {
    (void)in_sizes; (void)n_in; (void)out_size;
    const float* x  = (const float*)d_in[0];
    const float* Wq = (const float*)d_in[1];
    const float* Wk = (const float*)d_in[2];
    const float* Wv = (const float*)d_in[3];
    const float* Wo = (const float*)d_in[4];
    const float* bo = (const float*)d_in[5];
    float* out = (float*)d_out;

    convert_x_kernel<<<(Bq * Nq * DIMq) / 4 / 256, 256>>>(x);
    gram_kernel<<<dim3(Bq * Hq, GSPLIT), 256>>>(x);
    reduceG_kernel<<<(Bq * Hq * DHq * DHq) / 256, 256>>>();
    computeM_kernel<<<Bq * Hq, 256>>>(Wq, Wk, Wv);
    cudaFuncSetAttribute(expandP_kernel, cudaFuncAttributeMaxDynamicSharedMemorySize, 49920);
    expandP_kernel<<<dim3(Bq * Hq, 8), 256, 49920>>>(Wo);
    cudaFuncSetAttribute(gemm_hmma_kernel, cudaFuncAttributeMaxDynamicSharedMemorySize,
                         NSTAGES * STAGE_BYTES);
    gemm_hmma_kernel<<<dim3(DIMq / 128, Nq / 128, Bq), 256, NSTAGES * STAGE_BYTES>>>(bo, out);
}

// round 5
// speedup vs baseline: 2.5455x; 1.0102x over previous
#include <cuda_runtime.h>
#include <cuda_bf16.h>
#include <cstdint>

#define Bq 4
#define Nq 8192
#define DIMq 1024
#define Hq 16
#define DHq 64
#define GSPLIT 16

// ---------------- device scratch (no allocation allowed) ----------------
__device__ float g_Gpart[GSPLIT][Bq * Hq * DHq * DHq];   // 16 MB
__device__ __nv_bfloat16 g_Pthi[Bq * DIMq * DIMq];       // 8 MB  Pt[b][n][k]
__device__ __nv_bfloat16 g_Ptlo[Bq * DIMq * DIMq];       // 8 MB
__device__ __nv_bfloat16 g_xhi[Bq * Nq * DIMq];          // 64 MB
__device__ __nv_bfloat16 g_xlo[Bq * Nq * DIMq];          // 64 MB

// ---------------- PTX helpers ----------------
__device__ __forceinline__ uint32_t smem_u32(const void* p) {
    uint32_t a;
    asm("{ .reg .u64 t; cvta.to.shared.u64 t, %1; cvt.u32.u64 %0, t; }" : "=r"(a) : "l"(p));
    return a;
}

__device__ __forceinline__ void cpasync16(uint32_t saddr, const void* gptr) {
    asm volatile("cp.async.cg.shared.global [%0], [%1], 16;" :: "r"(saddr), "l"(gptr));
}
#define CP_COMMIT() asm volatile("cp.async.commit_group;" ::: "memory")
#define CP_WAIT(n)  asm volatile("cp.async.wait_group %0;" :: "n"(n) : "memory")

__device__ __forceinline__ void ldsm4(uint32_t* r, uint32_t addr) {
    asm volatile("ldmatrix.sync.aligned.m8n8.x4.shared.b16 {%0,%1,%2,%3}, [%4];"
                 : "=r"(r[0]), "=r"(r[1]), "=r"(r[2]), "=r"(r[3]) : "r"(addr));
}

__device__ __forceinline__ void mma16816(float* c, const uint32_t* a, const uint32_t* b) {
    asm volatile(
        "mma.sync.aligned.m16n8k16.row.col.f32.bf16.bf16.f32 "
        "{%0,%1,%2,%3}, {%4,%5,%6,%7}, {%8,%9}, {%0,%1,%2,%3};"
        : "+f"(c[0]), "+f"(c[1]), "+f"(c[2]), "+f"(c[3])
        : "r"(a[0]), "r"(a[1]), "r"(a[2]), "r"(a[3]), "r"(b[0]), "r"(b[1]));
}

// ---- packed f32x2 helpers for gram kernel ----
__device__ __forceinline__ unsigned long long pack2(float x) {
    unsigned long long v; unsigned u = __float_as_uint(x);
    asm("mov.b64 %0, {%1, %2};" : "=l"(v) : "r"(u), "r"(u));
    return v;
}
__device__ __forceinline__ unsigned long long ffma2(unsigned long long a,
                                                    unsigned long long b,
                                                    unsigned long long c) {
    unsigned long long d;
    asm("fma.rn.f32x2 %0, %1, %2, %3;" : "=l"(d) : "l"(a), "l"(b), "l"(c));
    return d;
}
__device__ __forceinline__ float2 unpack2(unsigned long long v) {
    unsigned lo, hi;
    asm("mov.b64 {%0, %1}, %2;" : "=r"(lo), "=r"(hi) : "l"(v));
    return make_float2(__uint_as_float(lo), __uint_as_float(hi));
}

// ============================================================
// Kernel 1: split x -> bf16 hi/lo
// ============================================================
__global__ __launch_bounds__(256) void convert_x_kernel(const float* __restrict__ x) {
    size_t i = ((size_t)blockIdx.x * 256 + threadIdx.x) * 4;
    float4 v = *(const float4*)(x + i);
    __nv_bfloat16 h0 = __float2bfloat16(v.x);
    __nv_bfloat16 h1 = __float2bfloat16(v.y);
    __nv_bfloat16 h2 = __float2bfloat16(v.z);
    __nv_bfloat16 h3 = __float2bfloat16(v.w);
    __nv_bfloat16 l0 = __float2bfloat16(v.x - __bfloat162float(h0));
    __nv_bfloat16 l1 = __float2bfloat16(v.y - __bfloat162float(h1));
    __nv_bfloat16 l2 = __float2bfloat16(v.z - __bfloat162float(h2));
    __nv_bfloat16 l3 = __float2bfloat16(v.w - __bfloat162float(h3));
    ushort4 hv = make_ushort4(__bfloat16_as_ushort(h0), __bfloat16_as_ushort(h1),
                              __bfloat16_as_ushort(h2), __bfloat16_as_ushort(h3));
    ushort4 lv = make_ushort4(__bfloat16_as_ushort(l0), __bfloat16_as_ushort(l1),
                              __bfloat16_as_ushort(l2), __bfloat16_as_ushort(l3));
    *(ushort4*)((unsigned short*)g_xhi + i) = hv;
    *(ushort4*)((unsigned short*)g_xlo + i) = lv;
}

// ============================================================
// Kernel 2: per-(b,h) Gram partials, split over N (FFMA2)
// ============================================================
__global__ __launch_bounds__(256) void gram_kernel(const float* __restrict__ x) {
    int bh = blockIdx.x;
    int sp = blockIdx.y;
    int b = bh >> 4, h = bh & 15;
    __shared__ float sx[8][64];
    int tid = threadIdx.x;
    int ty = tid >> 4, tx = tid & 15;
    int lr = tid >> 5, lc = (tid & 31) * 2;

    unsigned long long acc[4][2];
#pragma unroll
    for (int i = 0; i < 4; i++) { acc[i][0] = 0ull; acc[i][1] = 0ull; }

    const float* xb = x + ((size_t)b * Nq + (size_t)sp * (Nq / GSPLIT)) * DIMq + h * DHq;
    const int ITERS = (Nq / GSPLIT) / 8;

    for (int it = 0; it < ITERS; ++it) {
        *(float2*)&sx[lr][lc] = *(const float2*)(xb + (size_t)(it * 8 + lr) * DIMq + lc);
        __syncthreads();
#pragma unroll
        for (int r = 0; r < 8; r++) {
            float4 a4 = *(const float4*)&sx[r][ty * 4];
            ulonglong2 b2 = *(const ulonglong2*)&sx[r][tx * 4];
            unsigned long long ap;
            ap = pack2(a4.x); acc[0][0] = ffma2(ap, b2.x, acc[0][0]); acc[0][1] = ffma2(ap, b2.y, acc[0][1]);
            ap = pack2(a4.y); acc[1][0] = ffma2(ap, b2.x, acc[1][0]); acc[1][1] = ffma2(ap, b2.y, acc[1][1]);
            ap = pack2(a4.z); acc[2][0] = ffma2(ap, b2.x, acc[2][0]); acc[2][1] = ffma2(ap, b2.y, acc[2][1]);
            ap = pack2(a4.w); acc[3][0] = ffma2(ap, b2.x, acc[3][0]); acc[3][1] = ffma2(ap, b2.y, acc[3][1]);
        }
        __syncthreads();
    }

    float* dst = g_Gpart[sp] + (size_t)bh * 4096;
#pragma unroll
    for (int i = 0; i < 4; i++) {
        int row = ty * 4 + i;
        float2 v0 = unpack2(acc[i][0]);
        float2 v1 = unpack2(acc[i][1]);
        dst[row * 64 + tx * 4 + 0] = v0.x;
        dst[row * 64 + tx * 4 + 1] = v0.y;
        dst[row * 64 + tx * 4 + 2] = v1.x;
        dst[row * 64 + tx * 4 + 3] = v1.y;
    }
}

// ============================================================
// Kernel 3 (fused): reduce G, M = Wq^T Wk G Wv^T / N, expand with Wo
// one block per (b,h); dyn smem 49920 B
// ============================================================
__global__ __launch_bounds__(256) void computeMP_kernel(const float* __restrict__ Wq,
                                                        const float* __restrict__ Wk,
                                                        const float* __restrict__ Wv,
                                                        const float* __restrict__ Wo) {
    extern __shared__ float sm[];
    float* sA = sm;            // 64x65
    float* sB = sm + 4160;
    float* sC = sm + 8320;
    int bh = blockIdx.x;
    int b = bh >> 4, h = bh & 15;
    int tid = threadIdx.x;
    int ty = tid >> 4, tx = tid & 15;

    // load G (reducing partials) and Wv
    for (int i = tid; i < 4096; i += 256) {
        float s = 0.f;
#pragma unroll
        for (int p = 0; p < GSPLIT; p++) s += g_Gpart[p][(size_t)bh * 4096 + i];
        int r = i >> 6, c = i & 63;
        sA[r * 65 + c] = s;
        sB[r * 65 + c] = Wv[i];
    }
    __syncthreads();

    float acc[4][4];
    // Phase 1: T1[f][e] = sum_g G[f][g]*Wv[e][g] -> sC
#pragma unroll
    for (int i = 0; i < 4; i++)
#pragma unroll
        for (int j = 0; j < 4; j++) acc[i][j] = 0.f;
#pragma unroll 4
    for (int g = 0; g < 64; g++) {
        float a[4], bb[4];
#pragma unroll
        for (int i = 0; i < 4; i++) a[i] = sA[(ty * 4 + i) * 65 + g];
#pragma unroll
        for (int j = 0; j < 4; j++) bb[j] = sB[(tx * 4 + j) * 65 + g];
#pragma unroll
        for (int i = 0; i < 4; i++)
#pragma unroll
            for (int j = 0; j < 4; j++) acc[i][j] += a[i] * bb[j];
    }
    __syncthreads();
#pragma unroll
    for (int i = 0; i < 4; i++)
#pragma unroll
        for (int j = 0; j < 4; j++) sC[(ty * 4 + i) * 65 + tx * 4 + j] = acc[i][j];
    for (int i = tid; i < 4096; i += 256) {
        int r = i >> 6, c = i & 63;
        sA[r * 65 + c] = Wk[i];
    }
    __syncthreads();

    // Phase 2: T2[d][e] = sum_f Wk[d][f]*T1[f][e] -> sB
#pragma unroll
    for (int i = 0; i < 4; i++)
#pragma unroll
        for (int j = 0; j < 4; j++) acc[i][j] = 0.f;
#pragma unroll 4
    for (int f = 0; f < 64; f++) {
        float a[4], bb[4];
#pragma unroll
        for (int i = 0; i < 4; i++) a[i] = sA[(ty * 4 + i) * 65 + f];
#pragma unroll
        for (int j = 0; j < 4; j++) bb[j] = sC[f * 65 + tx * 4 + j];
#pragma unroll
        for (int i = 0; i < 4; i++)
#pragma unroll
            for (int j = 0; j < 4; j++) acc[i][j] += a[i] * bb[j];
    }
    __syncthreads();
#pragma unroll
    for (int i = 0; i < 4; i++)
#pragma unroll
        for (int j = 0; j < 4; j++) sB[(ty * 4 + i) * 65 + tx * 4 + j] = acc[i][j];
    for (int i = tid; i < 4096; i += 256) {
        int r = i >> 6, c = i & 63;
        sC[r * 65 + c] = Wq[i];
    }
    __syncthreads();

    // Phase 3: M[c][e] = (1/N) sum_d Wq[d][c]*T2[d][e]
#pragma unroll
    for (int i = 0; i < 4; i++)
#pragma unroll
        for (int j = 0; j < 4; j++) acc[i][j] = 0.f;
#pragma unroll 4
    for (int d = 0; d < 64; d++) {
        float a[4], bb[4];
#pragma unroll
        for (int i = 0; i < 4; i++) a[i] = sC[d * 65 + ty * 4 + i];
#pragma unroll
        for (int j = 0; j < 4; j++) bb[j] = sB[d * 65 + tx * 4 + j];
#pragma unroll
        for (int i = 0; i < 4; i++)
#pragma unroll
            for (int j = 0; j < 4; j++) acc[i][j] += a[i] * bb[j];
    }
    __syncthreads();
    const float sc = 1.0f / (float)Nq;
#pragma unroll
    for (int i = 0; i < 4; i++)
#pragma unroll
        for (int j = 0; j < 4; j++)
            sA[(ty * 4 + i) * 65 + tx * 4 + j] = acc[i][j] * sc;   // M in sA
    __syncthreads();

    // Expansion: Pt[b][i][h*64+c] = sum_e M[c][e] * Wo[i][h*64+e]
    float* sW = sB;  // spans sB..sC: 8320 floats = 128*65 exactly
    int ti = tid >> 3;  // 0..31 -> rows ii
    int tc = tid & 7;   // cols c
#pragma unroll 1
    for (int i0 = 0; i0 < DIMq; i0 += 128) {
        for (int idx = tid; idx < 128 * 64; idx += 256) {
            int ii = idx >> 6, e = idx & 63;
            sW[ii * 65 + e] = Wo[(size_t)(i0 + ii) * DIMq + h * DHq + e];
        }
        __syncthreads();

        float pacc[4][8];
#pragma unroll
        for (int i = 0; i < 4; i++)
#pragma unroll
            for (int j = 0; j < 8; j++) pacc[i][j] = 0.f;
#pragma unroll 4
        for (int e = 0; e < 64; e++) {
            float w[4], m[8];
#pragma unroll
            for (int i = 0; i < 4; i++) w[i] = sW[(ti * 4 + i) * 65 + e];
#pragma unroll
            for (int j = 0; j < 8; j++) m[j] = sA[(tc * 8 + j) * 65 + e];
#pragma unroll
            for (int i = 0; i < 4; i++)
#pragma unroll
                for (int j = 0; j < 8; j++) pacc[i][j] += w[i] * m[j];
        }
#pragma unroll
        for (int i = 0; i < 4; i++) {
            int ii = i0 + ti * 4 + i;
#pragma unroll
            for (int j = 0; j < 8; j++) {
                float v = pacc[i][j];
                size_t o = ((size_t)b << 20) + (size_t)ii * DIMq + (h * DHq + tc * 8 + j);
                __nv_bfloat16 hi = __float2bfloat16(v);
                g_Pthi[o] = hi;
                g_Ptlo[o] = __float2bfloat16(v - __bfloat162float(hi));
            }
        }
        __syncthreads();
    }
}

// ============================================================
// Kernel 4: HMMA GEMM  out[b] = x[b] @ P[b] + bo
// CTA 256x128, 512 thr (4x4 warps, 64x32 warp tiles), BK=32,
// 3-stage cp.async, 3-term bf16 split
// ============================================================
#define BM 256
#define BN 128
#define STAGE_BYTES 49152   // Ahi 16K | Alo 16K | Bhi 8K | Blo 8K
#define NSTAGES 3
#define KCHUNKS 32

__device__ __forceinline__ void issue_chunk(uint32_t sbase, const char* gAh,
                                            const char* gAl, const char* gBh,
                                            const char* gBl, int tid) {
#pragma unroll
    for (int j = 0; j < 2; j++) {
        int idx = j * 512 + tid;
        int row = idx >> 2, g = idx & 3;
        uint32_t so = row * 64 + (((g ^ ((row >> 1) & 3))) << 4);
        size_t go = (size_t)row * 2048 + g * 16;
        cpasync16(sbase + so, gAh + go);
        cpasync16(sbase + 16384 + so, gAl + go);
    }
    {
        int row = tid >> 2, g = tid & 3;
        uint32_t so = row * 64 + (((g ^ ((row >> 1) & 3))) << 4);
        size_t go = (size_t)row * 2048 + g * 16;
        cpasync16(sbase + 32768 + so, gBh + go);
        cpasync16(sbase + 40960 + so, gBl + go);
    }
}

__global__ __launch_bounds__(512, 1) void gemm_hmma_kernel(const float* __restrict__ bo,
                                                           float* __restrict__ out) {
    extern __shared__ __align__(128) char dsm[];
    uint32_t sbase = smem_u32(dsm);

    int tid = threadIdx.x;
    int warp = tid >> 5, lane = tid & 31;
    int wm = warp & 3;   // m offset 64*wm
    int wn = warp >> 2;  // n offset 32*wn
    int b = blockIdx.z;
    int m0 = blockIdx.y * BM;
    int n0 = blockIdx.x * BN;

    const char* gAh = (const char*)g_xhi + (((size_t)b * Nq + m0) * DIMq) * 2;
    const char* gAl = (const char*)g_xlo + (((size_t)b * Nq + m0) * DIMq) * 2;
    const char* gBh = (const char*)g_Pthi + (((size_t)b * DIMq + n0) * DIMq) * 2;
    const char* gBl = (const char*)g_Ptlo + (((size_t)b * DIMq + n0) * DIMq) * 2;

    float acc[4][4][4];
#pragma unroll
    for (int mt = 0; mt < 4; mt++)
#pragma unroll
        for (int j = 0; j < 4; j++)
#pragma unroll
            for (int q = 0; q < 4; q++) acc[mt][j][q] = 0.f;

    int rowA = wm * 64 + (lane & 15);                         // + mt*16
    int gA = (lane >> 4);                                     // + 2s
    int rowB = wn * 32 + ((lane >> 4) & 1) * 8 + (lane & 7);  // + jt*16
    int gB = ((lane >> 3) & 1);                               // + 2s

    issue_chunk(sbase + 0 * STAGE_BYTES, gAh, gAl, gBh, gBl, tid);
    CP_COMMIT();
    issue_chunk(sbase + 1 * STAGE_BYTES, gAh + 64, gAl + 64, gBh + 64, gBl + 64, tid);
    CP_COMMIT();

#pragma unroll 1
    for (int ki = 0; ki < KCHUNKS; ki++) {
        CP_WAIT(1);
        __syncthreads();
        if (ki + 2 < KCHUNKS) {
            int slot = (ki + 2) % NSTAGES;
            size_t off = (size_t)(ki + 2) * 64;
            issue_chunk(sbase + slot * STAGE_BYTES, gAh + off, gAl + off, gBh + off, gBl + off, tid);
        }
        CP_COMMIT();

        uint32_t st = sbase + (ki % NSTAGES) * STAGE_BYTES;
#pragma unroll
        for (int s = 0; s < 2; s++) {
            uint32_t bh[4][2], bl[4][2];
#pragma unroll
            for (int jt = 0; jt < 2; jt++) {
                int r = rowB + jt * 16;
                int gg = ((gB + 2 * s) ^ ((r >> 1) & 3)) << 4;
                uint32_t ad = st + 32768 + r * 64 + gg;
                uint32_t t0[4], t1[4];
                ldsm4(t0, ad);
                ldsm4(t1, ad + 8192);
                bh[jt * 2][0] = t0[0]; bh[jt * 2][1] = t0[1];
                bh[jt * 2 + 1][0] = t0[2]; bh[jt * 2 + 1][1] = t0[3];
                bl[jt * 2][0] = t1[0]; bl[jt * 2][1] = t1[1];
                bl[jt * 2 + 1][0] = t1[2]; bl[jt * 2 + 1][1] = t1[3];
            }
#pragma unroll
            for (int mt = 0; mt < 4; mt++) {
                uint32_t ah[4], al[4];
                int r = rowA + mt * 16;
                int gg = ((gA + 2 * s) ^ ((r >> 1) & 3)) << 4;
                uint32_t ad = st + r * 64 + gg;
                ldsm4(ah, ad);
                ldsm4(al, ad + 16384);
#pragma unroll
                for (int j = 0; j < 4; j++) {
                    mma16816(acc[mt][j], ah, bh[j]);
                    mma16816(acc[mt][j], ah, bl[j]);
                    mma16816(acc[mt][j], al, bh[j]);
                }
            }
        }
    }

    // epilogue
    int r0 = lane >> 2, cpair = (lane & 3) * 2;
#pragma unroll
    for (int j = 0; j < 4; j++) {
        int n = n0 + wn * 32 + j * 8 + cpair;
        float2 bb = *(const float2*)(bo + n);
#pragma unroll
        for (int mt = 0; mt < 4; mt++) {
            int m = m0 + wm * 64 + mt * 16 + r0;
            float2 o0 = make_float2(acc[mt][j][0] + bb.x, acc[mt][j][1] + bb.y);
            float2 o1 = make_float2(acc[mt][j][2] + bb.x, acc[mt][j][3] + bb.y);
            *(float2*)(out + ((size_t)b * Nq + m) * DIMq + n) = o0;
            *(float2*)(out + ((size_t)b * Nq + m + 8) * DIMq + n) = o1;
        }
    }
}

// ============================================================
extern "C" void kernel_launch(void* const* d_in, const int* in_sizes, int n_in,
                              void* d_out, int out_size) {
    (void)in_sizes; (void)n_in; (void)out_size;
    const float* x  = (const float*)d_in[0];
    const float* Wq = (const float*)d_in[1];
    const float* Wk = (const float*)d_in[2];
    const float* Wv = (const float*)d_in[3];
    const float* Wo = (const float*)d_in[4];
    const float* bo = (const float*)d_in[5];
    float* out = (float*)d_out;

    convert_x_kernel<<<(Bq * Nq * DIMq) / 4 / 256, 256>>>(x);
    gram_kernel<<<dim3(Bq * Hq, GSPLIT), 256>>>(x);
    cudaFuncSetAttribute(computeMP_kernel, cudaFuncAttributeMaxDynamicSharedMemorySize, 49920);
    computeMP_kernel<<<Bq * Hq, 256, 49920>>>(Wq, Wk, Wv, Wo);
    cudaFuncSetAttribute(gemm_hmma_kernel, cudaFuncAttributeMaxDynamicSharedMemorySize,
                         NSTAGES * STAGE_BYTES);
    gemm_hmma_kernel<<<dim3(DIMq / BN, Nq / BM, Bq), 512, NSTAGES * STAGE_BYTES>>>(bo, out);
}

// round 6
// speedup vs baseline: 3.3028x; 1.2975x over previous
#include <cuda_runtime.h>
#include <cuda_fp16.h>
#include <cstdint>

#define Bq 4
#define Nq 8192
#define DIMq 1024
#define Hq 16
#define DHq 64
#define GSPLIT 16

// ---------------- device scratch (no allocation allowed) ----------------
__device__ float g_Gpart[GSPLIT][Bq * Hq * DHq * DHq];   // 16 MB
__device__ __half g_Phi[Bq * DIMq * DIMq];               // 8 MB  Pt[b][n][k]
__device__ __half g_Plo[Bq * DIMq * DIMq];               // 8 MB
__device__ __half g_xhi[Bq * Nq * DIMq];                 // 64 MB

// ---------------- PTX helpers ----------------
__device__ __forceinline__ uint32_t smem_u32(const void* p) {
    uint32_t a;
    asm("{ .reg .u64 t; cvta.to.shared.u64 t, %1; cvt.u32.u64 %0, t; }" : "=r"(a) : "l"(p));
    return a;
}

__device__ __forceinline__ void cpasync16(uint32_t saddr, const void* gptr) {
    asm volatile("cp.async.cg.shared.global [%0], [%1], 16;" :: "r"(saddr), "l"(gptr));
}
#define CP_COMMIT() asm volatile("cp.async.commit_group;" ::: "memory")
#define CP_WAIT(n)  asm volatile("cp.async.wait_group %0;" :: "n"(n) : "memory")

__device__ __forceinline__ void ldsm4(uint32_t* r, uint32_t addr) {
    asm volatile("ldmatrix.sync.aligned.m8n8.x4.shared.b16 {%0,%1,%2,%3}, [%4];"
                 : "=r"(r[0]), "=r"(r[1]), "=r"(r[2]), "=r"(r[3]) : "r"(addr));
}

__device__ __forceinline__ void mma16816(float* c, const uint32_t* a, const uint32_t* b) {
    asm volatile(
        "mma.sync.aligned.m16n8k16.row.col.f32.f16.f16.f32 "
        "{%0,%1,%2,%3}, {%4,%5,%6,%7}, {%8,%9}, {%0,%1,%2,%3};"
        : "+f"(c[0]), "+f"(c[1]), "+f"(c[2]), "+f"(c[3])
        : "r"(a[0]), "r"(a[1]), "r"(a[2]), "r"(a[3]), "r"(b[0]), "r"(b[1]));
}

// ---- packed f32x2 helpers for gram kernel ----
__device__ __forceinline__ unsigned long long pack2(float x) {
    unsigned long long v; unsigned u = __float_as_uint(x);
    asm("mov.b64 %0, {%1, %2};" : "=l"(v) : "r"(u), "r"(u));
    return v;
}
__device__ __forceinline__ unsigned long long ffma2(unsigned long long a,
                                                    unsigned long long b,
                                                    unsigned long long c) {
    unsigned long long d;
    asm("fma.rn.f32x2 %0, %1, %2, %3;" : "=l"(d) : "l"(a), "l"(b), "l"(c));
    return d;
}
__device__ __forceinline__ float2 unpack2(unsigned long long v) {
    unsigned lo, hi;
    asm("mov.b64 {%0, %1}, %2;" : "=r"(lo), "=r"(hi) : "l"(v));
    return make_float2(__uint_as_float(lo), __uint_as_float(hi));
}

// ============================================================
// Kernel 1: x -> fp16
// ============================================================
__global__ __launch_bounds__(256) void convert_x_kernel(const float* __restrict__ x) {
    size_t i = ((size_t)blockIdx.x * 256 + threadIdx.x) * 8;
    float4 v0 = *(const float4*)(x + i);
    float4 v1 = *(const float4*)(x + i + 4);
    __half2 h0 = __floats2half2_rn(v0.x, v0.y);
    __half2 h1 = __floats2half2_rn(v0.z, v0.w);
    __half2 h2 = __floats2half2_rn(v1.x, v1.y);
    __half2 h3 = __floats2half2_rn(v1.z, v1.w);
    uint4 pk;
    pk.x = *(uint32_t*)&h0; pk.y = *(uint32_t*)&h1;
    pk.z = *(uint32_t*)&h2; pk.w = *(uint32_t*)&h3;
    *(uint4*)((__half*)g_xhi + i) = pk;
}

// ============================================================
// Kernel 2: per-(b,h) Gram partials, split over N (FFMA2)
// ============================================================
__global__ __launch_bounds__(256) void gram_kernel(const float* __restrict__ x) {
    int bh = blockIdx.x;
    int sp = blockIdx.y;
    int b = bh >> 4, h = bh & 15;
    __shared__ float sx[8][64];
    int tid = threadIdx.x;
    int ty = tid >> 4, tx = tid & 15;
    int lr = tid >> 5, lc = (tid & 31) * 2;

    unsigned long long acc[4][2];
#pragma unroll
    for (int i = 0; i < 4; i++) { acc[i][0] = 0ull; acc[i][1] = 0ull; }

    const float* xb = x + ((size_t)b * Nq + (size_t)sp * (Nq / GSPLIT)) * DIMq + h * DHq;
    const int ITERS = (Nq / GSPLIT) / 8;

    for (int it = 0; it < ITERS; ++it) {
        *(float2*)&sx[lr][lc] = *(const float2*)(xb + (size_t)(it * 8 + lr) * DIMq + lc);
        __syncthreads();
#pragma unroll
        for (int r = 0; r < 8; r++) {
            float4 a4 = *(const float4*)&sx[r][ty * 4];
            ulonglong2 b2 = *(const ulonglong2*)&sx[r][tx * 4];
            unsigned long long ap;
            ap = pack2(a4.x); acc[0][0] = ffma2(ap, b2.x, acc[0][0]); acc[0][1] = ffma2(ap, b2.y, acc[0][1]);
            ap = pack2(a4.y); acc[1][0] = ffma2(ap, b2.x, acc[1][0]); acc[1][1] = ffma2(ap, b2.y, acc[1][1]);
            ap = pack2(a4.z); acc[2][0] = ffma2(ap, b2.x, acc[2][0]); acc[2][1] = ffma2(ap, b2.y, acc[2][1]);
            ap = pack2(a4.w); acc[3][0] = ffma2(ap, b2.x, acc[3][0]); acc[3][1] = ffma2(ap, b2.y, acc[3][1]);
        }
        __syncthreads();
    }

    float* dst = g_Gpart[sp] + (size_t)bh * 4096;
#pragma unroll
    for (int i = 0; i < 4; i++) {
        int row = ty * 4 + i;
        float2 v0 = unpack2(acc[i][0]);
        float2 v1 = unpack2(acc[i][1]);
        dst[row * 64 + tx * 4 + 0] = v0.x;
        dst[row * 64 + tx * 4 + 1] = v0.y;
        dst[row * 64 + tx * 4 + 2] = v1.x;
        dst[row * 64 + tx * 4 + 3] = v1.y;
    }
}

// ============================================================
// Kernel 3 (fused): reduce G, M = Wq^T Wk G Wv^T / N, expand with Wo
// one block per (b,h); dyn smem 49920 B; emits fp16 Phi/Plo
// ============================================================
__global__ __launch_bounds__(256) void computeMP_kernel(const float* __restrict__ Wq,
                                                        const float* __restrict__ Wk,
                                                        const float* __restrict__ Wv,
                                                        const float* __restrict__ Wo) {
    extern __shared__ float sm[];
    float* sA = sm;            // 64x65
    float* sB = sm + 4160;
    float* sC = sm + 8320;
    int bh = blockIdx.x;
    int b = bh >> 4, h = bh & 15;
    int tid = threadIdx.x;
    int ty = tid >> 4, tx = tid & 15;

    for (int i = tid; i < 4096; i += 256) {
        float s = 0.f;
#pragma unroll
        for (int p = 0; p < GSPLIT; p++) s += g_Gpart[p][(size_t)bh * 4096 + i];
        int r = i >> 6, c = i & 63;
        sA[r * 65 + c] = s;
        sB[r * 65 + c] = Wv[i];
    }
    __syncthreads();

    float acc[4][4];
#pragma unroll
    for (int i = 0; i < 4; i++)
#pragma unroll
        for (int j = 0; j < 4; j++) acc[i][j] = 0.f;
#pragma unroll 4
    for (int g = 0; g < 64; g++) {
        float a[4], bb[4];
#pragma unroll
        for (int i = 0; i < 4; i++) a[i] = sA[(ty * 4 + i) * 65 + g];
#pragma unroll
        for (int j = 0; j < 4; j++) bb[j] = sB[(tx * 4 + j) * 65 + g];
#pragma unroll
        for (int i = 0; i < 4; i++)
#pragma unroll
            for (int j = 0; j < 4; j++) acc[i][j] += a[i] * bb[j];
    }
    __syncthreads();
#pragma unroll
    for (int i = 0; i < 4; i++)
#pragma unroll
        for (int j = 0; j < 4; j++) sC[(ty * 4 + i) * 65 + tx * 4 + j] = acc[i][j];
    for (int i = tid; i < 4096; i += 256) {
        int r = i >> 6, c = i & 63;
        sA[r * 65 + c] = Wk[i];
    }
    __syncthreads();

#pragma unroll
    for (int i = 0; i < 4; i++)
#pragma unroll
        for (int j = 0; j < 4; j++) acc[i][j] = 0.f;
#pragma unroll 4
    for (int f = 0; f < 64; f++) {
        float a[4], bb[4];
#pragma unroll
        for (int i = 0; i < 4; i++) a[i] = sA[(ty * 4 + i) * 65 + f];
#pragma unroll
        for (int j = 0; j < 4; j++) bb[j] = sC[f * 65 + tx * 4 + j];
#pragma unroll
        for (int i = 0; i < 4; i++)
#pragma unroll
            for (int j = 0; j < 4; j++) acc[i][j] += a[i] * bb[j];
    }
    __syncthreads();
#pragma unroll
    for (int i = 0; i < 4; i++)
#pragma unroll
        for (int j = 0; j < 4; j++) sB[(ty * 4 + i) * 65 + tx * 4 + j] = acc[i][j];
    for (int i = tid; i < 4096; i += 256) {
        int r = i >> 6, c = i & 63;
        sC[r * 65 + c] = Wq[i];
    }
    __syncthreads();

#pragma unroll
    for (int i = 0; i < 4; i++)
#pragma unroll
        for (int j = 0; j < 4; j++) acc[i][j] = 0.f;
#pragma unroll 4
    for (int d = 0; d < 64; d++) {
        float a[4], bb[4];
#pragma unroll
        for (int i = 0; i < 4; i++) a[i] = sC[d * 65 + ty * 4 + i];
#pragma unroll
        for (int j = 0; j < 4; j++) bb[j] = sB[d * 65 + tx * 4 + j];
#pragma unroll
        for (int i = 0; i < 4; i++)
#pragma unroll
            for (int j = 0; j < 4; j++) acc[i][j] += a[i] * bb[j];
    }
    __syncthreads();
    const float sc = 1.0f / (float)Nq;
#pragma unroll
    for (int i = 0; i < 4; i++)
#pragma unroll
        for (int j = 0; j < 4; j++)
            sA[(ty * 4 + i) * 65 + tx * 4 + j] = acc[i][j] * sc;   // M in sA
    __syncthreads();

    // Expansion: Pt[b][i][h*64+c] = sum_e M[c][e] * Wo[i][h*64+e]
    float* sW = sB;
    int ti = tid >> 3;
    int tc = tid & 7;
#pragma unroll 1
    for (int i0 = 0; i0 < DIMq; i0 += 128) {
        for (int idx = tid; idx < 128 * 64; idx += 256) {
            int ii = idx >> 6, e = idx & 63;
            sW[ii * 65 + e] = Wo[(size_t)(i0 + ii) * DIMq + h * DHq + e];
        }
        __syncthreads();

        float pacc[4][8];
#pragma unroll
        for (int i = 0; i < 4; i++)
#pragma unroll
            for (int j = 0; j < 8; j++) pacc[i][j] = 0.f;
#pragma unroll 4
        for (int e = 0; e < 64; e++) {
            float w[4], m[8];
#pragma unroll
            for (int i = 0; i < 4; i++) w[i] = sW[(ti * 4 + i) * 65 + e];
#pragma unroll
            for (int j = 0; j < 8; j++) m[j] = sA[(tc * 8 + j) * 65 + e];
#pragma unroll
            for (int i = 0; i < 4; i++)
#pragma unroll
                for (int j = 0; j < 8; j++) pacc[i][j] += w[i] * m[j];
        }
#pragma unroll
        for (int i = 0; i < 4; i++) {
            int ii = i0 + ti * 4 + i;
#pragma unroll
            for (int j = 0; j < 8; j++) {
                float v = pacc[i][j];
                size_t o = ((size_t)b << 20) + (size_t)ii * DIMq + (h * DHq + tc * 8 + j);
                __half hi = __float2half_rn(v);
                g_Phi[o] = hi;
                g_Plo[o] = __float2half_rn(v - __half2float(hi));
            }
        }
        __syncthreads();
    }
}

// ============================================================
// Kernel 4: fp16 HMMA GEMM  out[b] = xhi[b] @ (Phi+Plo)[b] + bo
// CTA 128x128, 256 thr (2x4 warps, 64x32 warp tiles), BK=32,
// 4-stage cp.async (96 KB), 2 CTAs/SM
// ============================================================
#define BM 128
#define BN 128
#define STAGE_BYTES 24576   // Ahi 8K | Bhi 8K | Blo 8K
#define NSTAGES 4
#define KCHUNKS 32

__device__ __forceinline__ void issue_chunk(uint32_t sbase, const char* gA,
                                            const char* gBh, const char* gBl, int tid) {
#pragma unroll
    for (int j = 0; j < 2; j++) {
        int idx = j * 256 + tid;
        int row = idx >> 2, g = idx & 3;
        uint32_t so = row * 64 + (((g ^ ((row >> 1) & 3))) << 4);
        size_t go = (size_t)row * 2048 + g * 16;
        cpasync16(sbase + so, gA + go);
        cpasync16(sbase + 8192 + so, gBh + go);
        cpasync16(sbase + 16384 + so, gBl + go);
    }
}

__global__ __launch_bounds__(256, 2) void gemm_hmma_kernel(const float* __restrict__ bo,
                                                           float* __restrict__ out) {
    extern __shared__ __align__(128) char dsm[];
    uint32_t sbase = smem_u32(dsm);

    int tid = threadIdx.x;
    int warp = tid >> 5, lane = tid & 31;
    int wm = warp & 1;   // m offset 64*wm
    int wn = warp >> 1;  // n offset 32*wn
    int b = blockIdx.z;
    int m0 = blockIdx.y * BM;
    int n0 = blockIdx.x * BN;

    const char* gA  = (const char*)g_xhi + (((size_t)b * Nq + m0) * DIMq) * 2;
    const char* gBh = (const char*)g_Phi + (((size_t)b * DIMq + n0) * DIMq) * 2;
    const char* gBl = (const char*)g_Plo + (((size_t)b * DIMq + n0) * DIMq) * 2;

    float acc[4][4][4];
#pragma unroll
    for (int mt = 0; mt < 4; mt++)
#pragma unroll
        for (int j = 0; j < 4; j++)
#pragma unroll
            for (int q = 0; q < 4; q++) acc[mt][j][q] = 0.f;

    int rowA = wm * 64 + (lane & 15);                         // + mt*16
    int gA_  = (lane >> 4);                                   // + 2s
    int rowB = wn * 32 + ((lane >> 4) & 1) * 8 + (lane & 7);  // + jt*16
    int gB_  = ((lane >> 3) & 1);                             // + 2s

    issue_chunk(sbase + 0 * STAGE_BYTES, gA, gBh, gBl, tid); CP_COMMIT();
    issue_chunk(sbase + 1 * STAGE_BYTES, gA + 64, gBh + 64, gBl + 64, tid); CP_COMMIT();
    issue_chunk(sbase + 2 * STAGE_BYTES, gA + 128, gBh + 128, gBl + 128, tid); CP_COMMIT();

#pragma unroll 1
    for (int ki = 0; ki < KCHUNKS; ki++) {
        CP_WAIT(2);
        __syncthreads();
        if (ki + 3 < KCHUNKS) {
            int slot = (ki + 3) & (NSTAGES - 1);
            size_t off = (size_t)(ki + 3) * 64;
            issue_chunk(sbase + slot * STAGE_BYTES, gA + off, gBh + off, gBl + off, tid);
        }
        CP_COMMIT();

        uint32_t st = sbase + (ki & (NSTAGES - 1)) * STAGE_BYTES;
#pragma unroll
        for (int s = 0; s < 2; s++) {
            uint32_t bh[4][2], bl[4][2];
#pragma unroll
            for (int jt = 0; jt < 2; jt++) {
                int r = rowB + jt * 16;
                int gg = ((gB_ + 2 * s) ^ ((r >> 1) & 3)) << 4;
                uint32_t ad = st + 8192 + r * 64 + gg;
                uint32_t t0[4], t1[4];
                ldsm4(t0, ad);
                ldsm4(t1, ad + 8192);
                bh[jt * 2][0] = t0[0]; bh[jt * 2][1] = t0[1];
                bh[jt * 2 + 1][0] = t0[2]; bh[jt * 2 + 1][1] = t0[3];
                bl[jt * 2][0] = t1[0]; bl[jt * 2][1] = t1[1];
                bl[jt * 2 + 1][0] = t1[2]; bl[jt * 2 + 1][1] = t1[3];
            }
#pragma unroll
            for (int mt = 0; mt < 4; mt++) {
                uint32_t ah[4];
                int r = rowA + mt * 16;
                int gg = ((gA_ + 2 * s) ^ ((r >> 1) & 3)) << 4;
                ldsm4(ah, st + r * 64 + gg);
#pragma unroll
                for (int j = 0; j < 4; j++) {
                    mma16816(acc[mt][j], ah, bh[j]);
                    mma16816(acc[mt][j], ah, bl[j]);
                }
            }
        }
    }

    // epilogue
    int r0 = lane >> 2, cpair = (lane & 3) * 2;
#pragma unroll
    for (int j = 0; j < 4; j++) {
        int n = n0 + wn * 32 + j * 8 + cpair;
        float2 bb = *(const float2*)(bo + n);
#pragma unroll
        for (int mt = 0; mt < 4; mt++) {
            int m = m0 + wm * 64 + mt * 16 + r0;
            float2 o0 = make_float2(acc[mt][j][0] + bb.x, acc[mt][j][1] + bb.y);
            float2 o1 = make_float2(acc[mt][j][2] + bb.x, acc[mt][j][3] + bb.y);
            *(float2*)(out + ((size_t)b * Nq + m) * DIMq + n) = o0;
            *(float2*)(out + ((size_t)b * Nq + m + 8) * DIMq + n) = o1;
        }
    }
}

// ============================================================
extern "C" void kernel_launch(void* const* d_in, const int* in_sizes, int n_in,
                              void* d_out, int out_size) {
    (void)in_sizes; (void)n_in; (void)out_size;
    const float* x  = (const float*)d_in[0];
    const float* Wq = (const float*)d_in[1];
    const float* Wk = (const float*)d_in[2];
    const float* Wv = (const float*)d_in[3];
    const float* Wo = (const float*)d_in[4];
    const float* bo = (const float*)d_in[5];
    float* out = (float*)d_out;

    convert_x_kernel<<<(Bq * Nq * DIMq) / 8 / 256, 256>>>(x);
    gram_kernel<<<dim3(Bq * Hq, GSPLIT), 256>>>(x);
    cudaFuncSetAttribute(computeMP_kernel, cudaFuncAttributeMaxDynamicSharedMemorySize, 49920);
    computeMP_kernel<<<Bq * Hq, 256, 49920>>>(Wq, Wk, Wv, Wo);
    cudaFuncSetAttribute(gemm_hmma_kernel, cudaFuncAttributeMaxDynamicSharedMemorySize,
                         NSTAGES * STAGE_BYTES);
    gemm_hmma_kernel<<<dim3(DIMq / BN, Nq / BM, Bq), 256, NSTAGES * STAGE_BYTES>>>(bo, out);
}

// round 7
// speedup vs baseline: 5.2499x; 1.5895x over previous
#include <cuda_runtime.h>
#include <cuda_fp16.h>
#include <cstdint>

#define Bq 4
#define Nq 8192
#define DIMq 1024
#define Hq 16
#define DHq 64
#define GSPLIT 16

// ---------------- device scratch (no allocation allowed) ----------------
__device__ float g_Gpart[GSPLIT][Bq * Hq * DHq * DHq];   // 16 MB
__device__ __half g_Phi[Bq * DIMq * DIMq];               // 8 MB  Pt[b][n][k]
__device__ __half g_xhi[Bq * Nq * DIMq];                 // 64 MB

// ---------------- PTX helpers ----------------
__device__ __forceinline__ uint32_t smem_u32(const void* p) {
    uint32_t a;
    asm("{ .reg .u64 t; cvta.to.shared.u64 t, %1; cvt.u32.u64 %0, t; }" : "=r"(a) : "l"(p));
    return a;
}

__device__ __forceinline__ void cpasync16(uint32_t saddr, const void* gptr) {
    asm volatile("cp.async.cg.shared.global [%0], [%1], 16;" :: "r"(saddr), "l"(gptr));
}
#define CP_COMMIT() asm volatile("cp.async.commit_group;" ::: "memory")
#define CP_WAIT(n)  asm volatile("cp.async.wait_group %0;" :: "n"(n) : "memory")

__device__ __forceinline__ void ldsm4(uint32_t* r, uint32_t addr) {
    asm volatile("ldmatrix.sync.aligned.m8n8.x4.shared.b16 {%0,%1,%2,%3}, [%4];"
                 : "=r"(r[0]), "=r"(r[1]), "=r"(r[2]), "=r"(r[3]) : "r"(addr));
}

__device__ __forceinline__ void mma16816(float* c, const uint32_t* a, const uint32_t* b) {
    asm volatile(
        "mma.sync.aligned.m16n8k16.row.col.f32.f16.f16.f32 "
        "{%0,%1,%2,%3}, {%4,%5,%6,%7}, {%8,%9}, {%0,%1,%2,%3};"
        : "+f"(c[0]), "+f"(c[1]), "+f"(c[2]), "+f"(c[3])
        : "r"(a[0]), "r"(a[1]), "r"(a[2]), "r"(a[3]), "r"(b[0]), "r"(b[1]));
}

// ---- packed f32x2 helpers for gram kernel ----
__device__ __forceinline__ unsigned long long pack2(float x) {
    unsigned long long v; unsigned u = __float_as_uint(x);
    asm("mov.b64 %0, {%1, %2};" : "=l"(v) : "r"(u), "r"(u));
    return v;
}
__device__ __forceinline__ unsigned long long ffma2(unsigned long long a,
                                                    unsigned long long b,
                                                    unsigned long long c) {
    unsigned long long d;
    asm("fma.rn.f32x2 %0, %1, %2, %3;" : "=l"(d) : "l"(a), "l"(b), "l"(c));
    return d;
}
__device__ __forceinline__ float2 unpack2(unsigned long long v) {
    unsigned lo, hi;
    asm("mov.b64 {%0, %1}, %2;" : "=r"(lo), "=r"(hi) : "l"(v));
    return make_float2(__uint_as_float(lo), __uint_as_float(hi));
}

// ============================================================
// Kernel 1 (fused): Gram partials + x -> fp16 conversion
// grid (64 bh, GSPLIT); each block converts exactly the slice it reads.
// ============================================================
__global__ __launch_bounds__(256) void gram_convert_kernel(const float* __restrict__ x) {
    int bh = blockIdx.x;
    int sp = blockIdx.y;
    int b = bh >> 4, h = bh & 15;
    __shared__ float sx[8][64];
    int tid = threadIdx.x;
    int ty = tid >> 4, tx = tid & 15;
    int lr = tid >> 5, lc = (tid & 31) * 2;

    unsigned long long acc[4][2];
#pragma unroll
    for (int i = 0; i < 4; i++) { acc[i][0] = 0ull; acc[i][1] = 0ull; }

    size_t rowbase = (size_t)b * Nq + (size_t)sp * (Nq / GSPLIT);
    const float* xb = x + rowbase * DIMq + h * DHq;
    __half* xo = (__half*)g_xhi + rowbase * DIMq + h * DHq;
    const int ITERS = (Nq / GSPLIT) / 8;

    for (int it = 0; it < ITERS; ++it) {
        float2 v = *(const float2*)(xb + (size_t)(it * 8 + lr) * DIMq + lc);
        *(float2*)&sx[lr][lc] = v;
        // fused fp16 conversion (covers all of x across the grid)
        __half2 hv = __floats2half2_rn(v.x, v.y);
        *(__half2*)(xo + (size_t)(it * 8 + lr) * DIMq + lc) = hv;
        __syncthreads();
#pragma unroll
        for (int r = 0; r < 8; r++) {
            float4 a4 = *(const float4*)&sx[r][ty * 4];
            ulonglong2 b2 = *(const ulonglong2*)&sx[r][tx * 4];
            unsigned long long ap;
            ap = pack2(a4.x); acc[0][0] = ffma2(ap, b2.x, acc[0][0]); acc[0][1] = ffma2(ap, b2.y, acc[0][1]);
            ap = pack2(a4.y); acc[1][0] = ffma2(ap, b2.x, acc[1][0]); acc[1][1] = ffma2(ap, b2.y, acc[1][1]);
            ap = pack2(a4.z); acc[2][0] = ffma2(ap, b2.x, acc[2][0]); acc[2][1] = ffma2(ap, b2.y, acc[2][1]);
            ap = pack2(a4.w); acc[3][0] = ffma2(ap, b2.x, acc[3][0]); acc[3][1] = ffma2(ap, b2.y, acc[3][1]);
        }
        __syncthreads();
    }

    float* dst = g_Gpart[sp] + (size_t)bh * 4096;
#pragma unroll
    for (int i = 0; i < 4; i++) {
        int row = ty * 4 + i;
        float2 v0 = unpack2(acc[i][0]);
        float2 v1 = unpack2(acc[i][1]);
        dst[row * 64 + tx * 4 + 0] = v0.x;
        dst[row * 64 + tx * 4 + 1] = v0.y;
        dst[row * 64 + tx * 4 + 2] = v1.x;
        dst[row * 64 + tx * 4 + 3] = v1.y;
    }
}

// ============================================================
// Kernel 2 (fused): reduce G, M = Wq^T Wk G Wv^T / N, expand with Wo
// grid (64 bh, 4): M computed redundantly; each block expands 2 of 8 chunks
// ============================================================
__global__ __launch_bounds__(256) void computeMP_kernel(const float* __restrict__ Wq,
                                                        const float* __restrict__ Wk,
                                                        const float* __restrict__ Wv,
                                                        const float* __restrict__ Wo) {
    extern __shared__ float sm[];
    float* sA = sm;            // 64x65
    float* sB = sm + 4160;
    float* sC = sm + 8320;
    int bh = blockIdx.x;
    int b = bh >> 4, h = bh & 15;
    int tid = threadIdx.x;
    int ty = tid >> 4, tx = tid & 15;

    for (int i = tid; i < 4096; i += 256) {
        float s = 0.f;
#pragma unroll
        for (int p = 0; p < GSPLIT; p++) s += g_Gpart[p][(size_t)bh * 4096 + i];
        int r = i >> 6, c = i & 63;
        sA[r * 65 + c] = s;
        sB[r * 65 + c] = Wv[i];
    }
    __syncthreads();

    float acc[4][4];
#pragma unroll
    for (int i = 0; i < 4; i++)
#pragma unroll
        for (int j = 0; j < 4; j++) acc[i][j] = 0.f;
#pragma unroll 4
    for (int g = 0; g < 64; g++) {
        float a[4], bb[4];
#pragma unroll
        for (int i = 0; i < 4; i++) a[i] = sA[(ty * 4 + i) * 65 + g];
#pragma unroll
        for (int j = 0; j < 4; j++) bb[j] = sB[(tx * 4 + j) * 65 + g];
#pragma unroll
        for (int i = 0; i < 4; i++)
#pragma unroll
            for (int j = 0; j < 4; j++) acc[i][j] += a[i] * bb[j];
    }
    __syncthreads();
#pragma unroll
    for (int i = 0; i < 4; i++)
#pragma unroll
        for (int j = 0; j < 4; j++) sC[(ty * 4 + i) * 65 + tx * 4 + j] = acc[i][j];
    for (int i = tid; i < 4096; i += 256) {
        int r = i >> 6, c = i & 63;
        sA[r * 65 + c] = Wk[i];
    }
    __syncthreads();

#pragma unroll
    for (int i = 0; i < 4; i++)
#pragma unroll
        for (int j = 0; j < 4; j++) acc[i][j] = 0.f;
#pragma unroll 4
    for (int f = 0; f < 64; f++) {
        float a[4], bb[4];
#pragma unroll
        for (int i = 0; i < 4; i++) a[i] = sA[(ty * 4 + i) * 65 + f];
#pragma unroll
        for (int j = 0; j < 4; j++) bb[j] = sC[f * 65 + tx * 4 + j];
#pragma unroll
        for (int i = 0; i < 4; i++)
#pragma unroll
            for (int j = 0; j < 4; j++) acc[i][j] += a[i] * bb[j];
    }
    __syncthreads();
#pragma unroll
    for (int i = 0; i < 4; i++)
#pragma unroll
        for (int j = 0; j < 4; j++) sB[(ty * 4 + i) * 65 + tx * 4 + j] = acc[i][j];
    for (int i = tid; i < 4096; i += 256) {
        int r = i >> 6, c = i & 63;
        sC[r * 65 + c] = Wq[i];
    }
    __syncthreads();

#pragma unroll
    for (int i = 0; i < 4; i++)
#pragma unroll
        for (int j = 0; j < 4; j++) acc[i][j] = 0.f;
#pragma unroll 4
    for (int d = 0; d < 64; d++) {
        float a[4], bb[4];
#pragma unroll
        for (int i = 0; i < 4; i++) a[i] = sC[d * 65 + ty * 4 + i];
#pragma unroll
        for (int j = 0; j < 4; j++) bb[j] = sB[d * 65 + tx * 4 + j];
#pragma unroll
        for (int i = 0; i < 4; i++)
#pragma unroll
            for (int j = 0; j < 4; j++) acc[i][j] += a[i] * bb[j];
    }
    __syncthreads();
    const float sc = 1.0f / (float)Nq;
#pragma unroll
    for (int i = 0; i < 4; i++)
#pragma unroll
        for (int j = 0; j < 4; j++)
            sA[(ty * 4 + i) * 65 + tx * 4 + j] = acc[i][j] * sc;   // M in sA
    __syncthreads();

    // Expansion: this block handles 2 chunks of 128 rows
    float* sW = sB;
    int ti = tid >> 3;
    int tc = tid & 7;
    int base = blockIdx.y * 256;
#pragma unroll 1
    for (int i0 = base; i0 < base + 256; i0 += 128) {
        for (int idx = tid; idx < 128 * 64; idx += 256) {
            int ii = idx >> 6, e = idx & 63;
            sW[ii * 65 + e] = Wo[(size_t)(i0 + ii) * DIMq + h * DHq + e];
        }
        __syncthreads();

        float pacc[4][8];
#pragma unroll
        for (int i = 0; i < 4; i++)
#pragma unroll
            for (int j = 0; j < 8; j++) pacc[i][j] = 0.f;
#pragma unroll 4
        for (int e = 0; e < 64; e++) {
            float w[4], m[8];
#pragma unroll
            for (int i = 0; i < 4; i++) w[i] = sW[(ti * 4 + i) * 65 + e];
#pragma unroll
            for (int j = 0; j < 8; j++) m[j] = sA[(tc * 8 + j) * 65 + e];
#pragma unroll
            for (int i = 0; i < 4; i++)
#pragma unroll
                for (int j = 0; j < 8; j++) pacc[i][j] += w[i] * m[j];
        }
#pragma unroll
        for (int i = 0; i < 4; i++) {
            int ii = i0 + ti * 4 + i;
#pragma unroll
            for (int j = 0; j < 8; j++) {
                size_t o = ((size_t)b << 20) + (size_t)ii * DIMq + (h * DHq + tc * 8 + j);
                g_Phi[o] = __float2half_rn(pacc[i][j]);
            }
        }
        __syncthreads();
    }
}

// ============================================================
// Kernel 3: fp16 HMMA GEMM  out[b] = xhi[b] @ Phi[b] + bo
// CTA 128x128, 256 thr (2x4 warps, 64x32 warp tiles), BK=32,
// 4-stage cp.async (64 KB), 2 CTAs/SM
// ============================================================
#define BM 128
#define BN 128
#define STAGE_BYTES 16384   // A 8K | B 8K
#define NSTAGES 4
#define KCHUNKS 32

__device__ __forceinline__ void issue_chunk(uint32_t sbase, const char* gA,
                                            const char* gB, int tid) {
#pragma unroll
    for (int j = 0; j < 2; j++) {
        int idx = j * 256 + tid;
        int row = idx >> 2, g = idx & 3;
        uint32_t so = row * 64 + (((g ^ ((row >> 1) & 3))) << 4);
        size_t go = (size_t)row * 2048 + g * 16;
        cpasync16(sbase + so, gA + go);
        cpasync16(sbase + 8192 + so, gB + go);
    }
}

__global__ __launch_bounds__(256, 2) void gemm_hmma_kernel(const float* __restrict__ bo,
                                                           float* __restrict__ out) {
    extern __shared__ __align__(128) char dsm[];
    uint32_t sbase = smem_u32(dsm);

    int tid = threadIdx.x;
    int warp = tid >> 5, lane = tid & 31;
    int wm = warp & 1;   // m offset 64*wm
    int wn = warp >> 1;  // n offset 32*wn
    int b = blockIdx.z;
    int m0 = blockIdx.y * BM;
    int n0 = blockIdx.x * BN;

    const char* gA = (const char*)g_xhi + (((size_t)b * Nq + m0) * DIMq) * 2;
    const char* gB = (const char*)g_Phi + (((size_t)b * DIMq + n0) * DIMq) * 2;

    float acc[4][4][4];
#pragma unroll
    for (int mt = 0; mt < 4; mt++)
#pragma unroll
        for (int j = 0; j < 4; j++)
#pragma unroll
            for (int q = 0; q < 4; q++) acc[mt][j][q] = 0.f;

    int rowA = wm * 64 + (lane & 15);                         // + mt*16
    int gA_  = (lane >> 4);                                   // + 2s
    int rowB = wn * 32 + ((lane >> 4) & 1) * 8 + (lane & 7);  // + jt*16
    int gB_  = ((lane >> 3) & 1);                             // + 2s

    issue_chunk(sbase + 0 * STAGE_BYTES, gA, gB, tid); CP_COMMIT();
    issue_chunk(sbase + 1 * STAGE_BYTES, gA + 64, gB + 64, tid); CP_COMMIT();
    issue_chunk(sbase + 2 * STAGE_BYTES, gA + 128, gB + 128, tid); CP_COMMIT();

#pragma unroll 1
    for (int ki = 0; ki < KCHUNKS; ki++) {
        CP_WAIT(2);
        __syncthreads();
        if (ki + 3 < KCHUNKS) {
            int slot = (ki + 3) & (NSTAGES - 1);
            size_t off = (size_t)(ki + 3) * 64;
            issue_chunk(sbase + slot * STAGE_BYTES, gA + off, gB + off, tid);
        }
        CP_COMMIT();

        uint32_t st = sbase + (ki & (NSTAGES - 1)) * STAGE_BYTES;
#pragma unroll
        for (int s = 0; s < 2; s++) {
            uint32_t bhf[4][2];
#pragma unroll
            for (int jt = 0; jt < 2; jt++) {
                int r = rowB + jt * 16;
                int gg = ((gB_ + 2 * s) ^ ((r >> 1) & 3)) << 4;
                uint32_t t0[4];
                ldsm4(t0, st + 8192 + r * 64 + gg);
                bhf[jt * 2][0] = t0[0]; bhf[jt * 2][1] = t0[1];
                bhf[jt * 2 + 1][0] = t0[2]; bhf[jt * 2 + 1][1] = t0[3];
            }
#pragma unroll
            for (int mt = 0; mt < 4; mt++) {
                uint32_t ah[4];
                int r = rowA + mt * 16;
                int gg = ((gA_ + 2 * s) ^ ((r >> 1) & 3)) << 4;
                ldsm4(ah, st + r * 64 + gg);
#pragma unroll
                for (int j = 0; j < 4; j++) {
                    mma16816(acc[mt][j], ah, bhf[j]);
                }
            }
        }
    }

    // epilogue
    int r0 = lane >> 2, cpair = (lane & 3) * 2;
#pragma unroll
    for (int j = 0; j < 4; j++) {
        int n = n0 + wn * 32 + j * 8 + cpair;
        float2 bb = *(const float2*)(bo + n);
#pragma unroll
        for (int mt = 0; mt < 4; mt++) {
            int m = m0 + wm * 64 + mt * 16 + r0;
            float2 o0 = make_float2(acc[mt][j][0] + bb.x, acc[mt][j][1] + bb.y);
            float2 o1 = make_float2(acc[mt][j][2] + bb.x, acc[mt][j][3] + bb.y);
            *(float2*)(out + ((size_t)b * Nq + m) * DIMq + n) = o0;
            *(float2*)(out + ((size_t)b * Nq + m + 8) * DIMq + n) = o1;
        }
    }
}

// ============================================================
extern "C" void kernel_launch(void* const* d_in, const int* in_sizes, int n_in,
                              void* d_out, int out_size) {
    (void)in_sizes; (void)n_in; (void)out_size;
    const float* x  = (const float*)d_in[0];
    const float* Wq = (const float*)d_in[1];
    const float* Wk = (const float*)d_in[2];
    const float* Wv = (const float*)d_in[3];
    const float* Wo = (const float*)d_in[4];
    const float* bo = (const float*)d_in[5];
    float* out = (float*)d_out;

    gram_convert_kernel<<<dim3(Bq * Hq, GSPLIT), 256>>>(x);
    cudaFuncSetAttribute(computeMP_kernel, cudaFuncAttributeMaxDynamicSharedMemorySize, 49920);
    computeMP_kernel<<<dim3(Bq * Hq, 4), 256, 49920>>>(Wq, Wk, Wv, Wo);
    cudaFuncSetAttribute(gemm_hmma_kernel, cudaFuncAttributeMaxDynamicSharedMemorySize,
                         NSTAGES * STAGE_BYTES);
    gemm_hmma_kernel<<<dim3(DIMq / BN, Nq / BM, Bq), 256, NSTAGES * STAGE_BYTES>>>(bo, out);
}

// round 8
// speedup vs baseline: 6.8854x; 1.3115x over previous
#include <cuda_runtime.h>
#include <cuda_fp16.h>
#include <cstdint>

#define Bq 4
#define Nq 8192
#define DIMq 1024
#define Hq 16
#define DHq 64
#define GSPLIT 32

// ---------------- device scratch (no allocation allowed) ----------------
__device__ float g_Gpart[GSPLIT][Bq * Hq * DHq * DHq];   // 32 MB
__device__ __half g_Phi[Bq * DIMq * DIMq];               // 8 MB  Pt[b][n][k]
__device__ __half g_xhi[Bq * Nq * DIMq];                 // 64 MB

// ---------------- PTX helpers ----------------
__device__ __forceinline__ uint32_t smem_u32(const void* p) {
    uint32_t a;
    asm("{ .reg .u64 t; cvta.to.shared.u64 t, %1; cvt.u32.u64 %0, t; }" : "=r"(a) : "l"(p));
    return a;
}

__device__ __forceinline__ void cpasync16(uint32_t saddr, const void* gptr) {
    asm volatile("cp.async.cg.shared.global [%0], [%1], 16;" :: "r"(saddr), "l"(gptr));
}
#define CP_COMMIT() asm volatile("cp.async.commit_group;" ::: "memory")
#define CP_WAIT(n)  asm volatile("cp.async.wait_group %0;" :: "n"(n) : "memory")

__device__ __forceinline__ void ldsm4(uint32_t* r, uint32_t addr) {
    asm volatile("ldmatrix.sync.aligned.m8n8.x4.shared.b16 {%0,%1,%2,%3}, [%4];"
                 : "=r"(r[0]), "=r"(r[1]), "=r"(r[2]), "=r"(r[3]) : "r"(addr));
}

__device__ __forceinline__ void ldsm4t(uint32_t* r, uint32_t addr) {
    asm volatile("ldmatrix.sync.aligned.m8n8.x4.trans.shared.b16 {%0,%1,%2,%3}, [%4];"
                 : "=r"(r[0]), "=r"(r[1]), "=r"(r[2]), "=r"(r[3]) : "r"(addr));
}

__device__ __forceinline__ void mma16816(float* c, const uint32_t* a, const uint32_t* b) {
    asm volatile(
        "mma.sync.aligned.m16n8k16.row.col.f32.f16.f16.f32 "
        "{%0,%1,%2,%3}, {%4,%5,%6,%7}, {%8,%9}, {%0,%1,%2,%3};"
        : "+f"(c[0]), "+f"(c[1]), "+f"(c[2]), "+f"(c[3])
        : "r"(a[0]), "r"(a[1]), "r"(a[2]), "r"(a[3]), "r"(b[0]), "r"(b[1]));
}

// ============================================================
// Kernel 1 (fused): x -> fp16 conversion + HMMA Gram partials
// grid (64 bh, GSPLIT), 256 thr. Tile [128 n][64 d] fp16 in smem,
// swizzled; both mma operands via ldmatrix.trans (K = n).
// ============================================================
__global__ __launch_bounds__(256) void gram_convert_kernel(const float* __restrict__ x) {
    __shared__ __align__(128) char gsm[2][16384];
    int bh = blockIdx.x;
    int sp = blockIdx.y;
    int b = bh >> 4, h = bh & 15;
    int tid = threadIdx.x;
    int warp = tid >> 5, lane = tid & 31;

    int d0 = (warp >> 1) * 16;
    int e0 = (warp & 1) * 32;

    size_t rowbase = (size_t)b * Nq + (size_t)sp * (Nq / GSPLIT);
    const float* xb = x + rowbase * DIMq + h * DHq;
    __half* xo = (__half*)g_xhi + rowbase * DIMq + h * DHq;

    int lf = tid & 15;    // float4 index within 64-col row
    int ln0 = tid >> 4;   // base row within 16-row pass group

    // ldsm.trans per-lane components
    int a_n = (lane & 7) + ((lane >> 4) & 1) * 8;
    int a_cb = d0 * 2 + ((lane >> 3) & 1) * 16;
    int b_n = (lane & 7) + ((lane >> 3) & 1) * 8;
    int b_cb0 = e0 * 2 + ((lane >> 4) & 1) * 16;
    int b_cb1 = (e0 + 16) * 2 + ((lane >> 4) & 1) * 16;

    float c[4][4];
#pragma unroll
    for (int j = 0; j < 4; j++)
#pragma unroll
        for (int q = 0; q < 4; q++) c[j][q] = 0.f;

    const int TILES = (Nq / GSPLIT) / 128;  // 2
    uint32_t bufu[2] = { smem_u32(gsm[0]), smem_u32(gsm[1]) };

    float4 v[8];
#pragma unroll
    for (int ps = 0; ps < 8; ps++)
        v[ps] = *(const float4*)(xb + (size_t)(ln0 + 16 * ps) * DIMq + lf * 4);
#pragma unroll
    for (int ps = 0; ps < 8; ps++) {
        int n = ln0 + 16 * ps;
        __half2 h0 = __floats2half2_rn(v[ps].x, v[ps].y);
        __half2 h1 = __floats2half2_rn(v[ps].z, v[ps].w);
        uint2 pk = make_uint2(*(uint32_t*)&h0, *(uint32_t*)&h1);
        uint32_t gr = (uint32_t)(((lf >> 1) ^ (n & 7)) * 16 + (lf & 1) * 8);
        *(uint2*)(gsm[0] + n * 128 + gr) = pk;
        *(uint2*)(xo + (size_t)n * DIMq + lf * 4) = pk;
    }
    __syncthreads();

#pragma unroll 1
    for (int t = 0; t < TILES; t++) {
        if (t + 1 < TILES) {
#pragma unroll
            for (int ps = 0; ps < 8; ps++)
                v[ps] = *(const float4*)(xb + (size_t)((t + 1) * 128 + ln0 + 16 * ps) * DIMq + lf * 4);
        }
        uint32_t sb = bufu[t & 1];
#pragma unroll
        for (int ks = 0; ks < 8; ks++) {
            int n0 = ks * 16;
            uint32_t a[4], t0[4], t1[4];
            {
                int r = n0 + a_n;
                uint32_t ad = sb + r * 128 + (((((uint32_t)a_cb) >> 4) ^ (uint32_t)(r & 7)) << 4);
                ldsm4t(a, ad);
            }
            {
                int r = n0 + b_n;
                uint32_t ad0 = sb + r * 128 + (((((uint32_t)b_cb0) >> 4) ^ (uint32_t)(r & 7)) << 4);
                ldsm4t(t0, ad0);
                uint32_t ad1 = sb + r * 128 + (((((uint32_t)b_cb1) >> 4) ^ (uint32_t)(r & 7)) << 4);
                ldsm4t(t1, ad1);
            }
            uint32_t bf0[2] = { t0[0], t0[1] };
            uint32_t bf1[2] = { t0[2], t0[3] };
            uint32_t bf2[2] = { t1[0], t1[1] };
            uint32_t bf3[2] = { t1[2], t1[3] };
            mma16816(c[0], a, bf0);
            mma16816(c[1], a, bf1);
            mma16816(c[2], a, bf2);
            mma16816(c[3], a, bf3);
        }
        if (t + 1 < TILES) {
#pragma unroll
            for (int ps = 0; ps < 8; ps++) {
                int n = ln0 + 16 * ps;
                __half2 h0 = __floats2half2_rn(v[ps].x, v[ps].y);
                __half2 h1 = __floats2half2_rn(v[ps].z, v[ps].w);
                uint2 pk = make_uint2(*(uint32_t*)&h0, *(uint32_t*)&h1);
                uint32_t gr = (uint32_t)(((lf >> 1) ^ (n & 7)) * 16 + (lf & 1) * 8);
                *(uint2*)(gsm[(t + 1) & 1] + n * 128 + gr) = pk;
                *(uint2*)(xo + (size_t)((t + 1) * 128 + n) * DIMq + lf * 4) = pk;
            }
        }
        __syncthreads();
    }

    float* dst = g_Gpart[sp] + (size_t)bh * 4096;
    int g = lane >> 2, tq = lane & 3;
#pragma unroll
    for (int j = 0; j < 4; j++) {
        int e = e0 + 8 * j + 2 * tq;
        *(float2*)(dst + (d0 + g) * 64 + e) = make_float2(c[j][0], c[j][1]);
        *(float2*)(dst + (d0 + g + 8) * 64 + e) = make_float2(c[j][2], c[j][3]);
    }
}

// ============================================================
// Kernel 2 (fused): reduce G, M = Wq^T Wk G Wv^T / N, expand with Wo
// grid (64 bh, 4)
// ============================================================
__global__ __launch_bounds__(256) void computeMP_kernel(const float* __restrict__ Wq,
                                                        const float* __restrict__ Wk,
                                                        const float* __restrict__ Wv,
                                                        const float* __restrict__ Wo) {
    extern __shared__ float sm[];
    float* sA = sm;            // 64x65
    float* sB = sm + 4160;
    float* sC = sm + 8320;
    int bh = blockIdx.x;
    int b = bh >> 4, h = bh & 15;
    int tid = threadIdx.x;
    int ty = tid >> 4, tx = tid & 15;

    for (int i = tid; i < 4096; i += 256) {
        float s = 0.f;
#pragma unroll
        for (int p = 0; p < GSPLIT; p++) s += g_Gpart[p][(size_t)bh * 4096 + i];
        int r = i >> 6, c = i & 63;
        sA[r * 65 + c] = s;
        sB[r * 65 + c] = Wv[i];
    }
    __syncthreads();

    float acc[4][4];
#pragma unroll
    for (int i = 0; i < 4; i++)
#pragma unroll
        for (int j = 0; j < 4; j++) acc[i][j] = 0.f;
#pragma unroll 4
    for (int g = 0; g < 64; g++) {
        float a[4], bb[4];
#pragma unroll
        for (int i = 0; i < 4; i++) a[i] = sA[(ty * 4 + i) * 65 + g];
#pragma unroll
        for (int j = 0; j < 4; j++) bb[j] = sB[(tx * 4 + j) * 65 + g];
#pragma unroll
        for (int i = 0; i < 4; i++)
#pragma unroll
            for (int j = 0; j < 4; j++) acc[i][j] += a[i] * bb[j];
    }
    __syncthreads();
#pragma unroll
    for (int i = 0; i < 4; i++)
#pragma unroll
        for (int j = 0; j < 4; j++) sC[(ty * 4 + i) * 65 + tx * 4 + j] = acc[i][j];
    for (int i = tid; i < 4096; i += 256) {
        int r = i >> 6, c = i & 63;
        sA[r * 65 + c] = Wk[i];
    }
    __syncthreads();

#pragma unroll
    for (int i = 0; i < 4; i++)
#pragma unroll
        for (int j = 0; j < 4; j++) acc[i][j] = 0.f;
#pragma unroll 4
    for (int f = 0; f < 64; f++) {
        float a[4], bb[4];
#pragma unroll
        for (int i = 0; i < 4; i++) a[i] = sA[(ty * 4 + i) * 65 + f];
#pragma unroll
        for (int j = 0; j < 4; j++) bb[j] = sC[f * 65 + tx * 4 + j];
#pragma unroll
        for (int i = 0; i < 4; i++)
#pragma unroll
            for (int j = 0; j < 4; j++) acc[i][j] += a[i] * bb[j];
    }
    __syncthreads();
#pragma unroll
    for (int i = 0; i < 4; i++)
#pragma unroll
        for (int j = 0; j < 4; j++) sB[(ty * 4 + i) * 65 + tx * 4 + j] = acc[i][j];
    for (int i = tid; i < 4096; i += 256) {
        int r = i >> 6, c = i & 63;
        sC[r * 65 + c] = Wq[i];
    }
    __syncthreads();

#pragma unroll
    for (int i = 0; i < 4; i++)
#pragma unroll
        for (int j = 0; j < 4; j++) acc[i][j] = 0.f;
#pragma unroll 4
    for (int d = 0; d < 64; d++) {
        float a[4], bb[4];
#pragma unroll
        for (int i = 0; i < 4; i++) a[i] = sC[d * 65 + ty * 4 + i];
#pragma unroll
        for (int j = 0; j < 4; j++) bb[j] = sB[d * 65 + tx * 4 + j];
#pragma unroll
        for (int i = 0; i < 4; i++)
#pragma unroll
            for (int j = 0; j < 4; j++) acc[i][j] += a[i] * bb[j];
    }
    __syncthreads();
    const float sc = 1.0f / (float)Nq;
#pragma unroll
    for (int i = 0; i < 4; i++)
#pragma unroll
        for (int j = 0; j < 4; j++)
            sA[(ty * 4 + i) * 65 + tx * 4 + j] = acc[i][j] * sc;   // M in sA
    __syncthreads();

    float* sW = sB;
    int ti = tid >> 3;
    int tc = tid & 7;
    int base = blockIdx.y * 256;
#pragma unroll 1
    for (int i0 = base; i0 < base + 256; i0 += 128) {
        for (int idx = tid; idx < 128 * 64; idx += 256) {
            int ii = idx >> 6, e = idx & 63;
            sW[ii * 65 + e] = Wo[(size_t)(i0 + ii) * DIMq + h * DHq + e];
        }
        __syncthreads();

        float pacc[4][8];
#pragma unroll
        for (int i = 0; i < 4; i++)
#pragma unroll
            for (int j = 0; j < 8; j++) pacc[i][j] = 0.f;
#pragma unroll 4
        for (int e = 0; e < 64; e++) {
            float w[4], m[8];
#pragma unroll
            for (int i = 0; i < 4; i++) w[i] = sW[(ti * 4 + i) * 65 + e];
#pragma unroll
            for (int j = 0; j < 8; j++) m[j] = sA[(tc * 8 + j) * 65 + e];
#pragma unroll
            for (int i = 0; i < 4; i++)
#pragma unroll
                for (int j = 0; j < 8; j++) pacc[i][j] += w[i] * m[j];
        }
#pragma unroll
        for (int i = 0; i < 4; i++) {
            int ii = i0 + ti * 4 + i;
#pragma unroll
            for (int j = 0; j < 8; j++) {
                size_t o = ((size_t)b << 20) + (size_t)ii * DIMq + (h * DHq + tc * 8 + j);
                g_Phi[o] = __float2half_rn(pacc[i][j]);
            }
        }
        __syncthreads();
    }
}

// ============================================================
// Kernel 3: fp16 HMMA GEMM  out[b] = xhi[b] @ Phi[b] + bo
// ============================================================
#define BM 128
#define BN 128
#define STAGE_BYTES 16384
#define NSTAGES 4
#define KCHUNKS 32

__device__ __forceinline__ void issue_chunk(uint32_t sbase, const char* gA,
                                            const char* gB, int tid) {
#pragma unroll
    for (int j = 0; j < 2; j++) {
        int idx = j * 256 + tid;
        int row = idx >> 2, g = idx & 3;
        uint32_t so = row * 64 + (((g ^ ((row >> 1) & 3))) << 4);
        size_t go = (size_t)row * 2048 + g * 16;
        cpasync16(sbase + so, gA + go);
        cpasync16(sbase + 8192 + so, gB + go);
    }
}

__global__ __launch_bounds__(256, 2) void gemm_hmma_kernel(const float* __restrict__ bo,
                                                           float* __restrict__ out) {
    extern __shared__ __align__(128) char dsm[];
    uint32_t sbase = smem_u32(dsm);

    int tid = threadIdx.x;
    int warp = tid >> 5, lane = tid & 31;
    int wm = warp & 1;
    int wn = warp >> 1;
    int b = blockIdx.z;
    int m0 = blockIdx.y * BM;
    int n0 = blockIdx.x * BN;

    const char* gA = (const char*)g_xhi + (((size_t)b * Nq + m0) * DIMq) * 2;
    const char* gB = (const char*)g_Phi + (((size_t)b * DIMq + n0) * DIMq) * 2;

    float acc[4][4][4];
#pragma unroll
    for (int mt = 0; mt < 4; mt++)
#pragma unroll
        for (int j = 0; j < 4; j++)
#pragma unroll
            for (int q = 0; q < 4; q++) acc[mt][j][q] = 0.f;

    int rowA = wm * 64 + (lane & 15);
    int gA_  = (lane >> 4);
    int rowB = wn * 32 + ((lane >> 4) & 1) * 8 + (lane & 7);
    int gB_  = ((lane >> 3) & 1);

    issue_chunk(sbase + 0 * STAGE_BYTES, gA, gB, tid); CP_COMMIT();
    issue_chunk(sbase + 1 * STAGE_BYTES, gA + 64, gB + 64, tid); CP_COMMIT();
    issue_chunk(sbase + 2 * STAGE_BYTES, gA + 128, gB + 128, tid); CP_COMMIT();

#pragma unroll 1
    for (int ki = 0; ki < KCHUNKS; ki++) {
        CP_WAIT(2);
        __syncthreads();
        if (ki + 3 < KCHUNKS) {
            int slot = (ki + 3) & (NSTAGES - 1);
            size_t off = (size_t)(ki + 3) * 64;
            issue_chunk(sbase + slot * STAGE_BYTES, gA + off, gB + off, tid);
        }
        CP_COMMIT();

        uint32_t st = sbase + (ki & (NSTAGES - 1)) * STAGE_BYTES;
#pragma unroll
        for (int s = 0; s < 2; s++) {
            uint32_t bhf[4][2];
#pragma unroll
            for (int jt = 0; jt < 2; jt++) {
                int r = rowB + jt * 16;
                int gg = ((gB_ + 2 * s) ^ ((r >> 1) & 3)) << 4;
                uint32_t t0[4];
                ldsm4(t0, st + 8192 + r * 64 + gg);
                bhf[jt * 2][0] = t0[0]; bhf[jt * 2][1] = t0[1];
                bhf[jt * 2 + 1][0] = t0[2]; bhf[jt * 2 + 1][1] = t0[3];
            }
#pragma unroll
            for (int mt = 0; mt < 4; mt++) {
                uint32_t ah[4];
                int r = rowA + mt * 16;
                int gg = ((gA_ + 2 * s) ^ ((r >> 1) & 3)) << 4;
                ldsm4(ah, st + r * 64 + gg);
#pragma unroll
                for (int j = 0; j < 4; j++) {
                    mma16816(acc[mt][j], ah, bhf[j]);
                }
            }
        }
    }

    int r0 = lane >> 2, cpair = (lane & 3) * 2;
#pragma unroll
    for (int j = 0; j < 4; j++) {
        int n = n0 + wn * 32 + j * 8 + cpair;
        float2 bb = *(const float2*)(bo + n);
#pragma unroll
        for (int mt = 0; mt < 4; mt++) {
            int m = m0 + wm * 64 + mt * 16 + r0;
            float2 o0 = make_float2(acc[mt][j][0] + bb.x, acc[mt][j][1] + bb.y);
            float2 o1 = make_float2(acc[mt][j][2] + bb.x, acc[mt][j][3] + bb.y);
            *(float2*)(out + ((size_t)b * Nq + m) * DIMq + n) = o0;
            *(float2*)(out + ((size_t)b * Nq + m + 8) * DIMq + n) = o1;
        }
    }
}

// ============================================================
extern "C" void kernel_launch(void* const* d_in, const int* in_sizes, int n_in,
                              void* d_out, int out_size) {
    (void)in_sizes; (void)n_in; (void)out_size;
    const float* x  = (const float*)d_in[0];
    const float* Wq = (const float*)d_in[1];
    const float* Wk = (const float*)d_in[2];
    const float* Wv = (const float*)d_in[3];
    const float* Wo = (const float*)d_in[4];
    const float* bo = (const float*)d_in[5];
    float* out = (float*)d_out;

    gram_convert_kernel<<<dim3(Bq * Hq, GSPLIT), 256>>>(x);
    cudaFuncSetAttribute(computeMP_kernel, cudaFuncAttributeMaxDynamicSharedMemorySize, 49920);
    computeMP_kernel<<<dim3(Bq * Hq, 4), 256, 49920>>>(Wq, Wk, Wv, Wo);
    cudaFuncSetAttribute(gemm_hmma_kernel, cudaFuncAttributeMaxDynamicSharedMemorySize,
                         NSTAGES * STAGE_BYTES);
    gemm_hmma_kernel<<<dim3(DIMq / BN, Nq / BM, Bq), 256, NSTAGES * STAGE_BYTES>>>(bo, out);
}